// round 12
// baseline (speedup 1.0000x reference)
#include <cuda_runtime.h>
#include <cuda_bf16.h>
#include <math.h>

typedef unsigned long long u64;

__device__ __forceinline__ u64 pack2(float lo, float hi) {
    u64 r; asm("mov.b64 %0,{%1,%2};" : "=l"(r) : "f"(lo), "f"(hi)); return r;
}
__device__ __forceinline__ void unpack2(u64 v, float& lo, float& hi) {
    asm("mov.b64 {%0,%1},%2;" : "=f"(lo), "=f"(hi) : "l"(v));
}
__device__ __forceinline__ u64 fma2(u64 a, u64 b, u64 c) {
    u64 d; asm("fma.rn.f32x2 %0,%1,%2,%3;" : "=l"(d) : "l"(a), "l"(b), "l"(c)); return d;
}

// ---------------- scratch (device globals; no allocations) ----------------
__device__ float g_bufA[4u * 256u * 64u * 64u];     // 16.8 MB
__device__ float g_bufB[4u * 256u * 64u * 64u];     // 16.8 MB
__device__ float g_V[16u * 256u * 4096u];           // 67 MB (Winograd V)
__device__ float g_M[16u * 256u * 4096u];           // 67 MB (Winograd M)
__device__ float g_U[9u * 1024u * 1024u];           // 36 MB (all layers' U)
__device__ float2 g_bnpart[8192];                   // per-block BN partials
__device__ float g_warp[4 * 2 * 64 * 64];
__device__ float g_stats[1024];                     // [mean(C) | rstd(C)]

// U offsets per layer (floats)
#define UO1  0u
#define UO2  1327104u      // + 36*144*256
#define UO3  3686400u      // + 36*256*256
#define UO4  6045696u
#define UF1  8404992u
#define UF2  8552448u      // + 36*64*64
#define UF3  8699904u
#define UF4  8847360u

// ---------------------------------------------------------------------------
// Kernel 1: fused correlation + softmax + expected grid position
// ---------------------------------------------------------------------------
__global__ __launch_bounds__(128) void corr_kernel(
    const float* __restrict__ f0, const float* __restrict__ f1,
    float* __restrict__ warp)
{
    const int b  = blockIdx.x >> 7;
    const int p0 = (blockIdx.x & 127) * 32;

    __shared__ __align__(16) float f0_s[64][32];
    __shared__ __align__(16) float f1_sc[64 * 128];
    __shared__ float m_s[32], l_s[32], sx_s[32], sy_s[32];

    const int t    = threadIdx.x;
    const int tx   = t & 15;
    const int ty   = t >> 4;
    const int q    = t >> 2;
    const int quad = t & 3;

    for (int i = t; i < 64 * 32; i += 128) {
        int p = i & 31, c = i >> 5;
        f0_s[c][p] = f0[(b * 64 + c) * 4096 + p0 + p];
    }
    if (t < 32) { m_s[t] = -1e30f; l_s[t] = 0.f; sx_s[t] = 0.f; sy_s[t] = 0.f; }
    __syncthreads();

    for (int j0 = 0; j0 < 4096; j0 += 128) {
        for (int i = t; i < 64 * 128; i += 128) {
            int j = i & 127, c = i >> 7;
            f1_sc[c * 128 + j] = f1[(b * 64 + c) * 4096 + j0 + j];
        }
        __syncthreads();

        u64 acc2[4][4];
        #pragma unroll
        for (int i = 0; i < 4; i++)
            #pragma unroll
            for (int jp = 0; jp < 4; jp++) acc2[i][jp] = 0ull;

        #pragma unroll 16
        for (int c = 0; c < 64; c++) {
            float4 a0 = *(const float4*)&f0_s[c][ty * 4];
            u64 ap[4] = { pack2(a0.x, a0.x), pack2(a0.y, a0.y),
                          pack2(a0.z, a0.z), pack2(a0.w, a0.w) };
            const u64* bp = (const u64*)&f1_sc[c * 128 + tx * 8];
            u64 b0 = bp[0], b1 = bp[1], b2 = bp[2], b3 = bp[3];
            #pragma unroll
            for (int i = 0; i < 4; i++) {
                acc2[i][0] = fma2(ap[i], b0, acc2[i][0]);
                acc2[i][1] = fma2(ap[i], b1, acc2[i][1]);
                acc2[i][2] = fma2(ap[i], b2, acc2[i][2]);
                acc2[i][3] = fma2(ap[i], b3, acc2[i][3]);
            }
        }
        __syncthreads();

        #pragma unroll
        for (int i = 0; i < 4; i++)
            #pragma unroll
            for (int jp = 0; jp < 4; jp++) {
                float lo, hi; unpack2(acc2[i][jp], lo, hi);
                f1_sc[(ty * 4 + i) * 132 + tx * 8 + 2 * jp]     = lo * 0.125f;
                f1_sc[(ty * 4 + i) * 132 + tx * 8 + 2 * jp + 1] = hi * 0.125f;
            }
        __syncthreads();

        float m_old = m_s[q];
        float sc[32];
        float tm = -1e30f;
        #pragma unroll
        for (int i = 0; i < 32; i++) {
            sc[i] = f1_sc[q * 132 + quad + 4 * i];
            tm = fmaxf(tm, sc[i]);
        }
        tm = fmaxf(tm, __shfl_xor_sync(0xffffffffu, tm, 1));
        tm = fmaxf(tm, __shfl_xor_sync(0xffffffffu, tm, 2));
        float nm = fmaxf(m_old, tm);

        float le = 0.f, lx = 0.f, ly = 0.f;
        #pragma unroll
        for (int i = 0; i < 32; i++) {
            int j   = j0 + quad + 4 * i;
            float e = __expf(sc[i] - nm);
            float gx = (float)((j & 63) * 2 + 1) * (1.f / 64.f) - 1.f;
            float gy = (float)((j >> 6) * 2 + 1) * (1.f / 64.f) - 1.f;
            le += e;
            lx = fmaf(e, gx, lx);
            ly = fmaf(e, gy, ly);
        }
        le += __shfl_xor_sync(0xffffffffu, le, 1);
        le += __shfl_xor_sync(0xffffffffu, le, 2);
        lx += __shfl_xor_sync(0xffffffffu, lx, 1);
        lx += __shfl_xor_sync(0xffffffffu, lx, 2);
        ly += __shfl_xor_sync(0xffffffffu, ly, 1);
        ly += __shfl_xor_sync(0xffffffffu, ly, 2);

        if (quad == 0) {
            float s = __expf(m_old - nm);
            l_s[q]  = l_s[q]  * s + le;
            sx_s[q] = sx_s[q] * s + lx;
            sy_s[q] = sy_s[q] * s + ly;
            m_s[q]  = nm;
        }
        __syncthreads();
    }

    if (t < 32) {
        float inv = 1.f / l_s[t];
        warp[(b * 2 + 0) * 4096 + p0 + t] = sx_s[t] * inv;
        warp[(b * 2 + 1) * 4096 + p0 + t] = sy_s[t] * inv;
    }
}

// ===========================================================================
// Winograd F(4x4, 3x3)
// ===========================================================================

__device__ __forceinline__ void gmul(float a0, float a1, float a2, float o[6]) {
    o[0] = 0.25f * a0;
    o[1] = (-1.f / 6.f) * (a0 + a1 + a2);
    o[2] = (1.f / 6.f) * (-a0 + a1 - a2);
    o[3] = (1.f / 24.f) * a0 + (1.f / 12.f) * a1 + (1.f / 6.f) * a2;
    o[4] = (1.f / 24.f) * a0 - (1.f / 12.f) * a1 + (1.f / 6.f) * a2;
    o[5] = a2;
}

// --- one fused weight transform for ALL 8 layers ---------------------------
__global__ void wino_wtrans_all(
    const float* __restrict__ cw1, const float* __restrict__ cw2,
    const float* __restrict__ cw3, const float* __restrict__ cw4,
    const float* __restrict__ fw1, const float* __restrict__ fw2,
    const float* __restrict__ fw3, const float* __restrict__ fw4,
    float* __restrict__ U)
{
    int idx = blockIdx.x * blockDim.x + threadIdx.x;
    const float* w; int Cin, K, Co; unsigned base;
    if      (idx < 36864)  { w = cw1; Cin = 130; K = 144; Co = 256; base = UO1; }
    else if (idx < 102400) { w = cw2; Cin = 256; K = 256; Co = 256; base = UO2; idx -= 36864; }
    else if (idx < 167936) { w = cw3; Cin = 256; K = 256; Co = 256; base = UO3; idx -= 102400; }
    else if (idx < 233472) { w = cw4; Cin = 256; K = 256; Co = 256; base = UO4; idx -= 167936; }
    else if (idx < 237568) { w = fw1; Cin = 50;  K = 64;  Co = 64;  base = UF1; idx -= 233472; }
    else if (idx < 241664) { w = fw2; Cin = 64;  K = 64;  Co = 64;  base = UF2; idx -= 237568; }
    else if (idx < 245760) { w = fw3; Cin = 64;  K = 64;  Co = 64;  base = UF3; idx -= 241664; }
    else if (idx < 249856) { w = fw4; Cin = 64;  K = 64;  Co = 64;  base = UF4; idx -= 245760; }
    else return;

    int co = idx % Co;
    int ci = idx / Co;

    float g[3][3];
    #pragma unroll
    for (int i = 0; i < 3; i++)
        #pragma unroll
        for (int j = 0; j < 3; j++)
            g[i][j] = (ci < Cin) ? w[(co * Cin + ci) * 9 + i * 3 + j] : 0.f;

    float u[6][3];
    #pragma unroll
    for (int j = 0; j < 3; j++) {
        float col[6];
        gmul(g[0][j], g[1][j], g[2][j], col);
        #pragma unroll
        for (int i = 0; i < 6; i++) u[i][j] = col[i];
    }
    #pragma unroll
    for (int i = 0; i < 6; i++) {
        float row[6];
        gmul(u[i][0], u[i][1], u[i][2], row);
        #pragma unroll
        for (int j = 0; j < 6; j++)
            U[base + ((size_t)(i * 6 + j) * K + ci) * Co + co] = row[j];
    }
}

__device__ __forceinline__ void btmul(const float x[6], float y[6]) {
    y[0] =  4.f * x[0] - 5.f * x[2] + x[4];
    y[1] = -4.f * x[1] - 4.f * x[2] + x[3] + x[4];
    y[2] =  4.f * x[1] - 4.f * x[2] - x[3] + x[4];
    y[3] = -2.f * x[1] -       x[2] + 2.f * x[3] + x[4];
    y[4] =  2.f * x[1] -       x[2] - 2.f * x[3] + x[4];
    y[5] =  4.f * x[1] - 5.f * x[3] + x[5];
}

// --- input transform: V = B^T d B; BN fold computed inline from partials ---
// Grid is exactly K*T/256 blocks; T % 256 == 0 so each block touches ONE ci.
__global__ __launch_bounds__(256) void wino_intrans(
    const float* __restrict__ in, const float2* __restrict__ part,
    int nparts, float invN, float* __restrict__ V,
    int Cin, int K, int H, int W, int tilesW, int T)
{
    int idx = blockIdx.x * 256 + threadIdx.x;
    int n  = idx % T;
    int ci = idx / T;

    __shared__ float s_mu, s_rs;
    const bool hasBN = (part != nullptr);
    if (hasBN) {
        if (threadIdx.x == 0) {
            int c0 = (blockIdx.x * 256) / T;
            if (c0 < Cin) {
                float s = 0.f, sq = 0.f;
                for (int j = 0; j < nparts; j++) {
                    float2 v = part[c0 * nparts + j];
                    s += v.x; sq += v.y;
                }
                float m   = s * invN;
                float var = sq * invN - m * m;
                s_mu = m;
                s_rs = rsqrtf(var + 1e-5f);
            } else { s_mu = 0.f; s_rs = 1.f; }
        }
        __syncthreads();
    }

    int tilesH = H >> 2;
    int tpb = tilesW * tilesH;
    int b  = n / tpb;
    int r  = n - b * tpb;
    int th = r / tilesW;
    int tw = r - th * tilesW;

    float d[6][6];
    if (ci < Cin) {
        const float* ip = in + ((size_t)b * Cin + ci) * H * W;
        float mu = hasBN ? s_mu : 0.f;
        float rs = hasBN ? s_rs : 0.f;
        int h0 = th * 4 - 1, w0 = tw * 4 - 1;
        #pragma unroll
        for (int i = 0; i < 6; i++) {
            int h = h0 + i;
            #pragma unroll
            for (int j = 0; j < 6; j++) {
                int w = w0 + j;
                float v = 0.f;
                if ((unsigned)h < (unsigned)H && (unsigned)w < (unsigned)W) {
                    v = ip[h * W + w];
                    if (hasBN) v = fmaxf((v - mu) * rs, 0.f);
                }
                d[i][j] = v;
            }
        }
    } else {
        #pragma unroll
        for (int i = 0; i < 6; i++)
            #pragma unroll
            for (int j = 0; j < 6; j++) d[i][j] = 0.f;
    }

    float tt[6][6];
    #pragma unroll
    for (int j = 0; j < 6; j++) {
        float col[6] = { d[0][j], d[1][j], d[2][j], d[3][j], d[4][j], d[5][j] };
        float o[6];
        btmul(col, o);
        #pragma unroll
        for (int i = 0; i < 6; i++) tt[i][j] = o[i];
    }
    float* Vp = V + (size_t)ci * T + n;
    size_t ps = (size_t)K * T;
    #pragma unroll
    for (int i = 0; i < 6; i++) {
        float o[6];
        btmul(tt[i], o);
        #pragma unroll
        for (int j = 0; j < 6; j++)
            Vp[(size_t)(i * 6 + j) * ps] = o[j];
    }
}

// --- coarse GEMM: tile 128co x 128n, 256 thr, 8x8/thread, K-chunk 16 -------
__global__ __launch_bounds__(256) void wino_gemm_c(
    const float* __restrict__ U, const float* __restrict__ V,
    float* __restrict__ M, int K, int Co, int T)
{
    const int xi = blockIdx.z;
    const int nb = blockIdx.x * 128;
    const int cb = blockIdx.y * 128;
    const float* Up = U + (size_t)xi * K * Co;
    const float* Vp = V + (size_t)xi * K * T;
    float*       Mp = M + (size_t)xi * Co * T;

    __shared__ __align__(16) float Us[16][128];
    __shared__ __align__(16) float Vs[16][128];

    const int t  = threadIdx.x;
    const int tn = (t & 15) * 8;
    const int tc = (t >> 4) * 8;

    const int kk = t >> 4;             // 0..15
    const int cc = (t & 15) * 8;       // 0..120

    float acc[8][8];
    #pragma unroll
    for (int i = 0; i < 8; i++)
        #pragma unroll
        for (int j = 0; j < 8; j++) acc[i][j] = 0.f;

    float4 ru0, ru1, rv0, rv1;
    ru0 = *(const float4*)&Up[(size_t)kk * Co + cb + cc];
    ru1 = *(const float4*)&Up[(size_t)kk * Co + cb + cc + 4];
    rv0 = *(const float4*)&Vp[(size_t)kk * T + nb + cc];
    rv1 = *(const float4*)&Vp[(size_t)kk * T + nb + cc + 4];

    const int nChunks = K >> 4;
    for (int c = 0; c < nChunks; c++) {
        if (c > 0) __syncthreads();
        *(float4*)&Us[kk][cc]     = ru0;
        *(float4*)&Us[kk][cc + 4] = ru1;
        *(float4*)&Vs[kk][cc]     = rv0;
        *(float4*)&Vs[kk][cc + 4] = rv1;
        __syncthreads();
        if (c + 1 < nChunks) {
            int k0 = (c + 1) * 16;
            ru0 = *(const float4*)&Up[(size_t)(k0 + kk) * Co + cb + cc];
            ru1 = *(const float4*)&Up[(size_t)(k0 + kk) * Co + cb + cc + 4];
            rv0 = *(const float4*)&Vp[(size_t)(k0 + kk) * T + nb + cc];
            rv1 = *(const float4*)&Vp[(size_t)(k0 + kk) * T + nb + cc + 4];
        }

        #pragma unroll
        for (int k = 0; k < 16; k++) {
            float a[8], bl[8];
            *(float4*)&a[0]  = *(const float4*)&Us[k][tc];
            *(float4*)&a[4]  = *(const float4*)&Us[k][tc + 4];
            *(float4*)&bl[0] = *(const float4*)&Vs[k][tn];
            *(float4*)&bl[4] = *(const float4*)&Vs[k][tn + 4];
            #pragma unroll
            for (int i = 0; i < 8; i++)
                #pragma unroll
                for (int j = 0; j < 8; j++)
                    acc[i][j] = fmaf(a[i], bl[j], acc[i][j]);
        }
    }

    #pragma unroll
    for (int i = 0; i < 8; i++) {
        float* o = &Mp[(size_t)(cb + tc + i) * T + nb + tn];
        *(float4*)o       = make_float4(acc[i][0], acc[i][1], acc[i][2], acc[i][3]);
        *(float4*)(o + 4) = make_float4(acc[i][4], acc[i][5], acc[i][6], acc[i][7]);
    }
}

// --- fine GEMM: tile 64co x 256n, 256 thr, 8x8/thread, K-chunk 16 ----------
__global__ __launch_bounds__(256) void wino_gemm_f(
    const float* __restrict__ U, const float* __restrict__ V,
    float* __restrict__ M, int K, int Co, int T)
{
    const int xi = blockIdx.z;
    const int nb = blockIdx.x * 256;
    const float* Up = U + (size_t)xi * K * Co;
    const float* Vp = V + (size_t)xi * K * T;
    float*       Mp = M + (size_t)xi * Co * T;

    __shared__ __align__(16) float Us[16][64];
    __shared__ __align__(16) float Vs[16][256];

    const int t  = threadIdx.x;
    const int tn = (t & 31) * 8;
    const int tc = (t >> 5) * 8;

    const int kk  = t >> 4;            // 0..15
    const int ucc = (t & 15) * 4;      // 0..60
    const int vnn = (t & 15) * 16;     // 0..240

    float acc[8][8];
    #pragma unroll
    for (int i = 0; i < 8; i++)
        #pragma unroll
        for (int j = 0; j < 8; j++) acc[i][j] = 0.f;

    float4 ru, rv[4];
    ru = *(const float4*)&Up[(size_t)kk * Co + ucc];
    #pragma unroll
    for (int q = 0; q < 4; q++)
        rv[q] = *(const float4*)&Vp[(size_t)kk * T + nb + vnn + q * 4];

    const int nChunks = K >> 4;
    for (int c = 0; c < nChunks; c++) {
        if (c > 0) __syncthreads();
        *(float4*)&Us[kk][ucc] = ru;
        #pragma unroll
        for (int q = 0; q < 4; q++)
            *(float4*)&Vs[kk][vnn + q * 4] = rv[q];
        __syncthreads();
        if (c + 1 < nChunks) {
            int k0 = (c + 1) * 16;
            ru = *(const float4*)&Up[(size_t)(k0 + kk) * Co + ucc];
            #pragma unroll
            for (int q = 0; q < 4; q++)
                rv[q] = *(const float4*)&Vp[(size_t)(k0 + kk) * T + nb + vnn + q * 4];
        }

        #pragma unroll
        for (int k = 0; k < 16; k++) {
            float a[8], bl[8];
            *(float4*)&a[0]  = *(const float4*)&Us[k][tc];
            *(float4*)&a[4]  = *(const float4*)&Us[k][tc + 4];
            *(float4*)&bl[0] = *(const float4*)&Vs[k][tn];
            *(float4*)&bl[4] = *(const float4*)&Vs[k][tn + 4];
            #pragma unroll
            for (int i = 0; i < 8; i++)
                #pragma unroll
                for (int j = 0; j < 8; j++)
                    acc[i][j] = fmaf(a[i], bl[j], acc[i][j]);
        }
    }

    #pragma unroll
    for (int i = 0; i < 8; i++) {
        float* o = &Mp[(size_t)(tc + i) * T + nb + tn];
        *(float4*)o       = make_float4(acc[i][0], acc[i][1], acc[i][2], acc[i][3]);
        *(float4*)(o + 4) = make_float4(acc[i][4], acc[i][5], acc[i][6], acc[i][7]);
    }
}

__device__ __forceinline__ void atmul(const float m[6], float y[4]) {
    y[0] = m[0] + m[1] + m[2] + m[3] + m[4];
    y[1] = m[1] - m[2] + 2.f * m[3] - 2.f * m[4];
    y[2] = m[1] + m[2] + 4.f * m[3] + 4.f * m[4];
    y[3] = m[1] - m[2] + 8.f * m[3] - 8.f * m[4] + m[5];
}

// --- output transform + block-reduced BN partial (1 per block) -------------
// Grid = Co*T/256; T % 256 == 0 so each block covers ONE co.
__global__ __launch_bounds__(256) void wino_outtrans(
    const float* __restrict__ M, float* __restrict__ out,
    float2* __restrict__ part, int Co, int H, int W, int tilesW, int T)
{
    int idx = blockIdx.x * 256 + threadIdx.x;
    int n  = idx % T;
    int co = idx / T;

    int tilesH = H >> 2;
    int tpb = tilesW * tilesH;
    int b  = n / tpb;
    int r  = n - b * tpb;
    int th = r / tilesW;
    int tw = r - th * tilesW;

    float m[6][6];
    const float* Mp = M + (size_t)co * T + n;
    size_t ps = (size_t)Co * T;
    #pragma unroll
    for (int i = 0; i < 6; i++)
        #pragma unroll
        for (int j = 0; j < 6; j++)
            m[i][j] = Mp[(size_t)(i * 6 + j) * ps];

    float s[4][6];
    #pragma unroll
    for (int j = 0; j < 6; j++) {
        float col[6] = { m[0][j], m[1][j], m[2][j], m[3][j], m[4][j], m[5][j] };
        float o[4];
        atmul(col, o);
        #pragma unroll
        for (int i = 0; i < 4; i++) s[i][j] = o[i];
    }

    float sum = 0.f, sq = 0.f;
    float* op = out + (((size_t)b * Co + co) * H + th * 4) * W + tw * 4;
    #pragma unroll
    for (int i = 0; i < 4; i++) {
        float o[4];
        atmul(s[i], o);
        op[i * W + 0] = o[0];
        op[i * W + 1] = o[1];
        op[i * W + 2] = o[2];
        op[i * W + 3] = o[3];
        #pragma unroll
        for (int j = 0; j < 4; j++) { sum += o[j]; sq = fmaf(o[j], o[j], sq); }
    }

    #pragma unroll
    for (int off = 16; off > 0; off >>= 1) {
        sum += __shfl_xor_sync(0xffffffffu, sum, off);
        sq  += __shfl_xor_sync(0xffffffffu, sq,  off);
    }
    __shared__ float2 red[8];
    if ((threadIdx.x & 31) == 0) red[threadIdx.x >> 5] = make_float2(sum, sq);
    __syncthreads();
    if (threadIdx.x == 0) {
        float ts = 0.f, tq = 0.f;
        #pragma unroll
        for (int i = 0; i < 8; i++) { ts += red[i].x; tq += red[i].y; }
        part[blockIdx.x] = make_float2(ts, tq);
    }
}

// --- finalize BN stats from partials (for the 1x1 heads) -------------------
__global__ void bn_finalize(const float2* __restrict__ part, float* __restrict__ stats,
                            int C, int nparts, float invN)
{
    int c = threadIdx.x;
    if (c >= C) return;
    float s = 0.f, sq = 0.f;
    for (int j = 0; j < nparts; j++) {
        float2 v = part[c * nparts + j];
        s += v.x; sq += v.y;
    }
    float m   = s * invN;
    float var = sq * invN - m * m;
    stats[c]     = m;
    stats[C + c] = rsqrtf(var + 1e-5f);
}

// ---------------------------------------------------------------------------
// fused concat assembly (copy + gridsample + coords)
// ---------------------------------------------------------------------------
__device__ __forceinline__ float gs_sample(const float* __restrict__ ip,
                                           float gx, float gy, int H, int W)
{
    float x = (gx + 1.f) * (W * 0.5f) - 0.5f;
    float y = (gy + 1.f) * (H * 0.5f) - 0.5f;
    float x0f = floorf(x), y0f = floorf(y);
    float wx = x - x0f, wy = y - y0f;
    int x0 = (int)x0f, y0 = (int)y0f;
    auto samp = [&](int yi, int xi) -> float {
        bool valid = (xi >= 0) && (xi < W) && (yi >= 0) && (yi < H);
        int yc = min(max(yi, 0), H - 1);
        int xc = min(max(xi, 0), W - 1);
        return valid ? ip[yc * W + xc] : 0.f;
    };
    return samp(y0,     x0    ) * (1.f - wx) * (1.f - wy)
         + samp(y0,     x0 + 1) * wx         * (1.f - wy)
         + samp(y0 + 1, x0    ) * (1.f - wx) * wy
         + samp(y0 + 1, x0 + 1) * wx         * wy;
}

__global__ void concat_coarse(const float* __restrict__ f0c, const float* __restrict__ f1c,
                              const float* __restrict__ warp, float* __restrict__ dst)
{
    const int HW = 4096;
    int idx = blockIdx.x * blockDim.x + threadIdx.x;
    if (idx >= 4 * 130 * HW) return;
    int p = idx % HW;
    int c = (idx / HW) % 130;
    int b = idx / (HW * 130);

    float v;
    if (c < 64) {
        v = f0c[((size_t)b * 64 + c) * HW + p];
    } else if (c < 128) {
        float gx = warp[(b * 2 + 0) * HW + p];
        float gy = warp[(b * 2 + 1) * HW + p];
        v = gs_sample(f1c + ((size_t)b * 64 + (c - 64)) * HW, gx, gy, 64, 64);
    } else {
        v = warp[(b * 2 + (c - 128)) * HW + p];
    }
    dst[((size_t)b * 130 + c) * HW + p] = v;
}

__global__ void concat_fine(const float* __restrict__ f0f, const float* __restrict__ f1f,
                            const float* __restrict__ up, float* __restrict__ dst)
{
    const int HW = 16384;
    int idx = blockIdx.x * blockDim.x + threadIdx.x;
    if (idx >= 4 * 50 * HW) return;
    int p = idx % HW;
    int c = (idx / HW) % 50;
    int b = idx / (HW * 50);

    float v;
    if (c < 24) {
        v = f0f[((size_t)b * 24 + c) * HW + p];
    } else if (c < 48) {
        float gx = up[((size_t)b * 3 + 0) * HW + p];
        float gy = up[((size_t)b * 3 + 1) * HW + p];
        v = gs_sample(f1f + ((size_t)b * 24 + (c - 24)) * HW, gx, gy, 128, 128);
    } else {
        v = up[((size_t)b * 3 + (c - 48)) * HW + p];
    }
    dst[((size_t)b * 50 + c) * HW + p] = v;
}

// ---------------------------------------------------------------------------
__global__ void upsample2x_kernel(const float* __restrict__ src, float* __restrict__ dst,
                                  int B_, int C, int Hi, int Wi)
{
    int Ho = Hi * 2, Wo = Wi * 2;
    int idx = blockIdx.x * blockDim.x + threadIdx.x;
    if (idx >= B_ * C * Ho * Wo) return;
    int wo = idx % Wo;
    int ho = (idx / Wo) % Ho;
    int bc = idx / (Wo * Ho);

    float sy = ho * 0.5f - 0.25f;
    float sx = wo * 0.5f - 0.25f;
    float fy = sy - floorf(sy);
    float fx = sx - floorf(sx);
    int y0 = (int)floorf(sy), x0 = (int)floorf(sx);
    int y0c = min(max(y0, 0), Hi - 1), y1c = min(max(y0 + 1, 0), Hi - 1);
    int x0c = min(max(x0, 0), Wi - 1), x1c = min(max(x0 + 1, 0), Wi - 1);

    const float* sp = src + bc * Hi * Wi;
    float v = sp[y0c * Wi + x0c] * (1.f - fy) * (1.f - fx)
            + sp[y0c * Wi + x1c] * (1.f - fy) * fx
            + sp[y1c * Wi + x0c] * fy * (1.f - fx)
            + sp[y1c * Wi + x1c] * fy * fx;
    dst[idx] = v;
}

// 1x1 conv to 3 ch + bias + base add, BN+ReLU fold on x via stats
__global__ void conv1x1_3_kernel(
    const float* __restrict__ x, const float* __restrict__ stats,
    const float* __restrict__ w5, const float* __restrict__ b5,
    const float* __restrict__ base, int baseC, int baseStrideB,
    float* __restrict__ out, int Cin, int HW, int B_)
{
    int idx = blockIdx.x * blockDim.x + threadIdx.x;
    if (idx >= B_ * HW) return;
    int b = idx / HW, p = idx - b * HW;

    float a0 = 0.f, a1 = 0.f, a2 = 0.f;
    const float* xp = x + (size_t)b * Cin * HW + p;
    for (int ci = 0; ci < Cin; ci++) {
        float v = xp[(size_t)ci * HW];
        v = fmaxf((v - __ldg(&stats[ci])) * __ldg(&stats[Cin + ci]), 0.f);
        a0 = fmaf(v, __ldg(&w5[ci]),            a0);
        a1 = fmaf(v, __ldg(&w5[Cin + ci]),      a1);
        a2 = fmaf(v, __ldg(&w5[2 * Cin + ci]),  a2);
    }
    float b0v = base[b * baseStrideB + p];
    float b1v = base[b * baseStrideB + HW + p];
    float b2v = (baseC > 2) ? base[b * baseStrideB + 2 * HW + p] : 0.f;

    out[(size_t)b * 3 * HW + p]           = a0 + __ldg(&b5[0]) + b0v;
    out[(size_t)b * 3 * HW + HW + p]      = a1 + __ldg(&b5[1]) + b1v;
    out[(size_t)b * 3 * HW + 2 * HW + p]  = a2 + __ldg(&b5[2]) + b2v;
}

// ---------------------------------------------------------------------------
// host-side helper: one Winograd F(4,3) conv layer (+ fused BN handling)
// ---------------------------------------------------------------------------
static void wino_layer(const float* x, const float* Ubase, const float2* partIn,
                       float* out, float* V, float* M, float2* partOut,
                       int Cin, int K, int Co, int H, int W)
{
    int tilesW = W >> 2, tilesH = H >> 2;
    int T = 4 * tilesW * tilesH;
    float invN = 1.f / (float)(T * 16);

    wino_intrans<<<K * T / 256, 256>>>(x, partIn, T / 256, invN, V,
                                       Cin, K, H, W, tilesW, T);
    if (Co == 256) {
        dim3 gg(T / 128, Co / 128, 36);
        wino_gemm_c<<<gg, 256>>>(Ubase, V, M, K, Co, T);
    } else {
        dim3 gg(T / 256, 1, 36);
        wino_gemm_f<<<gg, 256>>>(Ubase, V, M, K, Co, T);
    }
    wino_outtrans<<<Co * T / 256, 256>>>(M, out, partOut, Co, H, W, tilesW, T);
}

// ---------------------------------------------------------------------------
extern "C" void kernel_launch(void* const* d_in, const int* in_sizes, int n_in,
                              void* d_out, int out_size)
{
    const float* f0c = (const float*)d_in[0];
    const float* f1c = (const float*)d_in[1];
    const float* f0f = (const float*)d_in[2];
    const float* f1f = (const float*)d_in[3];
    const float* cw1 = (const float*)d_in[4];
    const float* cw2 = (const float*)d_in[5];
    const float* cw3 = (const float*)d_in[6];
    const float* cw4 = (const float*)d_in[7];
    const float* cw5 = (const float*)d_in[8];
    const float* cb5 = (const float*)d_in[9];
    const float* fw1 = (const float*)d_in[10];
    const float* fw2 = (const float*)d_in[11];
    const float* fw3 = (const float*)d_in[12];
    const float* fw4 = (const float*)d_in[13];
    const float* fw5 = (const float*)d_in[14];
    const float* fb5 = (const float*)d_in[15];

    float *A, *Bb, *V, *M, *U, *warp, *stats;
    float2* part;
    cudaGetSymbolAddress((void**)&A,     g_bufA);
    cudaGetSymbolAddress((void**)&Bb,    g_bufB);
    cudaGetSymbolAddress((void**)&V,     g_V);
    cudaGetSymbolAddress((void**)&M,     g_M);
    cudaGetSymbolAddress((void**)&U,     g_U);
    cudaGetSymbolAddress((void**)&part,  g_bnpart);
    cudaGetSymbolAddress((void**)&warp,  g_warp);
    cudaGetSymbolAddress((void**)&stats, g_stats);

    float* outC = (float*)d_out;                 // (4,3,64,64)
    float* outF = outC + 4 * 3 * 64 * 64;        // (4,3,128,128)

    const int HWc = 64 * 64, HWf = 128 * 128;

    // ---- all weight transforms up front (one kernel) ----
    wino_wtrans_all<<<(249856 + 255) / 256, 256>>>(cw1, cw2, cw3, cw4,
                                                   fw1, fw2, fw3, fw4, U);

    // ---- coarse stage ----
    corr_kernel<<<512, 128>>>(f0c, f1c, warp);

    concat_coarse<<<(4 * 130 * HWc + 255) / 256, 256>>>(f0c, f1c, warp, A);

    wino_layer(A,  U + UO1, nullptr, Bb, V, M, part, 130, 144, 256, 64, 64);
    wino_layer(Bb, U + UO2, part,    A,  V, M, part, 256, 256, 256, 64, 64);
    wino_layer(A,  U + UO3, part,    Bb, V, M, part, 256, 256, 256, 64, 64);
    wino_layer(Bb, U + UO4, part,    A,  V, M, part, 256, 256, 256, 64, 64);

    bn_finalize<<<1, 256>>>(part, stats, 256, 4, 1.f / 16384.f);
    conv1x1_3_kernel<<<(4 * HWc + 127) / 128, 128>>>(
        A, stats, cw5, cb5, warp, 2, 2 * HWc, outC, 256, HWc, 4);

    // ---- fine stage ----
    upsample2x_kernel<<<(4 * 3 * HWf + 255) / 256, 256>>>(outC, outF, 4, 3, 64, 64);

    concat_fine<<<(4 * 50 * HWf + 255) / 256, 256>>>(f0f, f1f, outF, Bb);

    wino_layer(Bb, U + UF1, nullptr, A,  V, M, part, 50, 64, 64, 128, 128);
    wino_layer(A,  U + UF2, part,    Bb, V, M, part, 64, 64, 64, 128, 128);
    wino_layer(Bb, U + UF3, part,    A,  V, M, part, 64, 64, 64, 128, 128);
    wino_layer(A,  U + UF4, part,    Bb, V, M, part, 64, 64, 64, 128, 128);

    bn_finalize<<<1, 256>>>(part, stats, 64, 16, 1.f / 65536.f);
    conv1x1_3_kernel<<<(4 * HWf + 127) / 128, 128>>>(
        Bb, stats, fw5, fb5, outF, 3, 3 * HWf, outF, 64, HWf, 4);
}

// round 13
// speedup vs baseline: 1.0636x; 1.0636x over previous
#include <cuda_runtime.h>
#include <cuda_bf16.h>
#include <math.h>

typedef unsigned long long u64;

__device__ __forceinline__ u64 pack2(float lo, float hi) {
    u64 r; asm("mov.b64 %0,{%1,%2};" : "=l"(r) : "f"(lo), "f"(hi)); return r;
}
__device__ __forceinline__ void unpack2(u64 v, float& lo, float& hi) {
    asm("mov.b64 {%0,%1},%2;" : "=f"(lo), "=f"(hi) : "l"(v));
}
__device__ __forceinline__ u64 fma2(u64 a, u64 b, u64 c) {
    u64 d; asm("fma.rn.f32x2 %0,%1,%2,%3;" : "=l"(d) : "l"(a), "l"(b), "l"(c)); return d;
}

// ---------------- scratch (device globals; no allocations) ----------------
__device__ float g_bufA[4u * 256u * 64u * 64u];     // 16.8 MB
__device__ float g_bufB[4u * 256u * 64u * 64u];     // 16.8 MB
__device__ float g_V[16u * 256u * 4096u];           // 67 MB (Winograd V)
__device__ float g_M[16u * 256u * 4096u];           // 67 MB (Winograd M)
__device__ float g_U[9u * 1024u * 1024u];           // 36 MB (all layers' U)
__device__ float2 g_bnpart[8192];                   // per-block BN partials
__device__ float g_warp[4 * 2 * 64 * 64];
__device__ float g_stats[1024];                     // [mean(C) | rstd(C)]

// U offsets per layer (floats)
#define UO1  0u
#define UO2  1327104u      // + 36*144*256
#define UO3  3686400u      // + 36*256*256
#define UO4  6045696u
#define UF1  8404992u
#define UF2  8552448u      // + 36*64*64
#define UF3  8699904u
#define UF4  8847360u

// ---------------------------------------------------------------------------
// Kernel 1: fused correlation + softmax + expected grid position
// ---------------------------------------------------------------------------
__global__ __launch_bounds__(128) void corr_kernel(
    const float* __restrict__ f0, const float* __restrict__ f1,
    float* __restrict__ warp)
{
    const int b  = blockIdx.x >> 7;
    const int p0 = (blockIdx.x & 127) * 32;

    __shared__ __align__(16) float f0_s[64][32];
    __shared__ __align__(16) float f1_sc[64 * 128];
    __shared__ float m_s[32], l_s[32], sx_s[32], sy_s[32];

    const int t    = threadIdx.x;
    const int tx   = t & 15;
    const int ty   = t >> 4;
    const int q    = t >> 2;
    const int quad = t & 3;

    for (int i = t; i < 64 * 32; i += 128) {
        int p = i & 31, c = i >> 5;
        f0_s[c][p] = f0[(b * 64 + c) * 4096 + p0 + p];
    }
    if (t < 32) { m_s[t] = -1e30f; l_s[t] = 0.f; sx_s[t] = 0.f; sy_s[t] = 0.f; }
    __syncthreads();

    for (int j0 = 0; j0 < 4096; j0 += 128) {
        for (int i = t; i < 64 * 128; i += 128) {
            int j = i & 127, c = i >> 7;
            f1_sc[c * 128 + j] = f1[(b * 64 + c) * 4096 + j0 + j];
        }
        __syncthreads();

        u64 acc2[4][4];
        #pragma unroll
        for (int i = 0; i < 4; i++)
            #pragma unroll
            for (int jp = 0; jp < 4; jp++) acc2[i][jp] = 0ull;

        #pragma unroll 16
        for (int c = 0; c < 64; c++) {
            float4 a0 = *(const float4*)&f0_s[c][ty * 4];
            u64 ap[4] = { pack2(a0.x, a0.x), pack2(a0.y, a0.y),
                          pack2(a0.z, a0.z), pack2(a0.w, a0.w) };
            const u64* bp = (const u64*)&f1_sc[c * 128 + tx * 8];
            u64 b0 = bp[0], b1 = bp[1], b2 = bp[2], b3 = bp[3];
            #pragma unroll
            for (int i = 0; i < 4; i++) {
                acc2[i][0] = fma2(ap[i], b0, acc2[i][0]);
                acc2[i][1] = fma2(ap[i], b1, acc2[i][1]);
                acc2[i][2] = fma2(ap[i], b2, acc2[i][2]);
                acc2[i][3] = fma2(ap[i], b3, acc2[i][3]);
            }
        }
        __syncthreads();

        #pragma unroll
        for (int i = 0; i < 4; i++)
            #pragma unroll
            for (int jp = 0; jp < 4; jp++) {
                float lo, hi; unpack2(acc2[i][jp], lo, hi);
                f1_sc[(ty * 4 + i) * 132 + tx * 8 + 2 * jp]     = lo * 0.125f;
                f1_sc[(ty * 4 + i) * 132 + tx * 8 + 2 * jp + 1] = hi * 0.125f;
            }
        __syncthreads();

        float m_old = m_s[q];
        float sc[32];
        float tm = -1e30f;
        #pragma unroll
        for (int i = 0; i < 32; i++) {
            sc[i] = f1_sc[q * 132 + quad + 4 * i];
            tm = fmaxf(tm, sc[i]);
        }
        tm = fmaxf(tm, __shfl_xor_sync(0xffffffffu, tm, 1));
        tm = fmaxf(tm, __shfl_xor_sync(0xffffffffu, tm, 2));
        float nm = fmaxf(m_old, tm);

        float le = 0.f, lx = 0.f, ly = 0.f;
        #pragma unroll
        for (int i = 0; i < 32; i++) {
            int j   = j0 + quad + 4 * i;
            float e = __expf(sc[i] - nm);
            float gx = (float)((j & 63) * 2 + 1) * (1.f / 64.f) - 1.f;
            float gy = (float)((j >> 6) * 2 + 1) * (1.f / 64.f) - 1.f;
            le += e;
            lx = fmaf(e, gx, lx);
            ly = fmaf(e, gy, ly);
        }
        le += __shfl_xor_sync(0xffffffffu, le, 1);
        le += __shfl_xor_sync(0xffffffffu, le, 2);
        lx += __shfl_xor_sync(0xffffffffu, lx, 1);
        lx += __shfl_xor_sync(0xffffffffu, lx, 2);
        ly += __shfl_xor_sync(0xffffffffu, ly, 1);
        ly += __shfl_xor_sync(0xffffffffu, ly, 2);

        if (quad == 0) {
            float s = __expf(m_old - nm);
            l_s[q]  = l_s[q]  * s + le;
            sx_s[q] = sx_s[q] * s + lx;
            sy_s[q] = sy_s[q] * s + ly;
            m_s[q]  = nm;
        }
        __syncthreads();
    }

    if (t < 32) {
        float inv = 1.f / l_s[t];
        warp[(b * 2 + 0) * 4096 + p0 + t] = sx_s[t] * inv;
        warp[(b * 2 + 1) * 4096 + p0 + t] = sy_s[t] * inv;
    }
}

// ===========================================================================
// Winograd F(4x4, 3x3)
// ===========================================================================

__device__ __forceinline__ void gmul(float a0, float a1, float a2, float o[6]) {
    o[0] = 0.25f * a0;
    o[1] = (-1.f / 6.f) * (a0 + a1 + a2);
    o[2] = (1.f / 6.f) * (-a0 + a1 - a2);
    o[3] = (1.f / 24.f) * a0 + (1.f / 12.f) * a1 + (1.f / 6.f) * a2;
    o[4] = (1.f / 24.f) * a0 - (1.f / 12.f) * a1 + (1.f / 6.f) * a2;
    o[5] = a2;
}

// --- one fused weight transform for ALL 8 layers ---------------------------
__global__ void wino_wtrans_all(
    const float* __restrict__ cw1, const float* __restrict__ cw2,
    const float* __restrict__ cw3, const float* __restrict__ cw4,
    const float* __restrict__ fw1, const float* __restrict__ fw2,
    const float* __restrict__ fw3, const float* __restrict__ fw4,
    float* __restrict__ U)
{
    int idx = blockIdx.x * blockDim.x + threadIdx.x;
    const float* w; int Cin, K, Co; unsigned base;
    if      (idx < 36864)  { w = cw1; Cin = 130; K = 144; Co = 256; base = UO1; }
    else if (idx < 102400) { w = cw2; Cin = 256; K = 256; Co = 256; base = UO2; idx -= 36864; }
    else if (idx < 167936) { w = cw3; Cin = 256; K = 256; Co = 256; base = UO3; idx -= 102400; }
    else if (idx < 233472) { w = cw4; Cin = 256; K = 256; Co = 256; base = UO4; idx -= 167936; }
    else if (idx < 237568) { w = fw1; Cin = 50;  K = 64;  Co = 64;  base = UF1; idx -= 233472; }
    else if (idx < 241664) { w = fw2; Cin = 64;  K = 64;  Co = 64;  base = UF2; idx -= 237568; }
    else if (idx < 245760) { w = fw3; Cin = 64;  K = 64;  Co = 64;  base = UF3; idx -= 241664; }
    else if (idx < 249856) { w = fw4; Cin = 64;  K = 64;  Co = 64;  base = UF4; idx -= 245760; }
    else return;

    int co = idx % Co;
    int ci = idx / Co;

    float g[3][3];
    #pragma unroll
    for (int i = 0; i < 3; i++)
        #pragma unroll
        for (int j = 0; j < 3; j++)
            g[i][j] = (ci < Cin) ? w[(co * Cin + ci) * 9 + i * 3 + j] : 0.f;

    float u[6][3];
    #pragma unroll
    for (int j = 0; j < 3; j++) {
        float col[6];
        gmul(g[0][j], g[1][j], g[2][j], col);
        #pragma unroll
        for (int i = 0; i < 6; i++) u[i][j] = col[i];
    }
    #pragma unroll
    for (int i = 0; i < 6; i++) {
        float row[6];
        gmul(u[i][0], u[i][1], u[i][2], row);
        #pragma unroll
        for (int j = 0; j < 6; j++)
            U[base + ((size_t)(i * 6 + j) * K + ci) * Co + co] = row[j];
    }
}

__device__ __forceinline__ void btmul(const float x[6], float y[6]) {
    y[0] =  4.f * x[0] - 5.f * x[2] + x[4];
    y[1] = -4.f * x[1] - 4.f * x[2] + x[3] + x[4];
    y[2] =  4.f * x[1] - 4.f * x[2] - x[3] + x[4];
    y[3] = -2.f * x[1] -       x[2] + 2.f * x[3] + x[4];
    y[4] =  2.f * x[1] -       x[2] - 2.f * x[3] + x[4];
    y[5] =  4.f * x[1] - 5.f * x[3] + x[5];
}

// --- input transform: V = B^T d B; BN fold computed inline from partials ---
// Grid is exactly K*T/256 blocks; T % 256 == 0 so each block touches ONE ci.
__global__ __launch_bounds__(256) void wino_intrans(
    const float* __restrict__ in, const float2* __restrict__ part,
    int nparts, float invN, float* __restrict__ V,
    int Cin, int K, int H, int W, int tilesW, int T)
{
    int idx = blockIdx.x * 256 + threadIdx.x;
    int n  = idx % T;
    int ci = idx / T;

    __shared__ float s_mu, s_rs;
    const bool hasBN = (part != nullptr);
    if (hasBN) {
        if (threadIdx.x == 0) {
            int c0 = (blockIdx.x * 256) / T;
            if (c0 < Cin) {
                float s = 0.f, sq = 0.f;
                for (int j = 0; j < nparts; j++) {
                    float2 v = part[c0 * nparts + j];
                    s += v.x; sq += v.y;
                }
                float m   = s * invN;
                float var = sq * invN - m * m;
                s_mu = m;
                s_rs = rsqrtf(var + 1e-5f);
            } else { s_mu = 0.f; s_rs = 1.f; }
        }
        __syncthreads();
    }

    int tilesH = H >> 2;
    int tpb = tilesW * tilesH;
    int b  = n / tpb;
    int r  = n - b * tpb;
    int th = r / tilesW;
    int tw = r - th * tilesW;

    float d[6][6];
    if (ci < Cin) {
        const float* ip = in + ((size_t)b * Cin + ci) * H * W;
        float mu = hasBN ? s_mu : 0.f;
        float rs = hasBN ? s_rs : 0.f;
        int h0 = th * 4 - 1, w0 = tw * 4 - 1;
        #pragma unroll
        for (int i = 0; i < 6; i++) {
            int h = h0 + i;
            #pragma unroll
            for (int j = 0; j < 6; j++) {
                int w = w0 + j;
                float v = 0.f;
                if ((unsigned)h < (unsigned)H && (unsigned)w < (unsigned)W) {
                    v = ip[h * W + w];
                    if (hasBN) v = fmaxf((v - mu) * rs, 0.f);
                }
                d[i][j] = v;
            }
        }
    } else {
        #pragma unroll
        for (int i = 0; i < 6; i++)
            #pragma unroll
            for (int j = 0; j < 6; j++) d[i][j] = 0.f;
    }

    float tt[6][6];
    #pragma unroll
    for (int j = 0; j < 6; j++) {
        float col[6] = { d[0][j], d[1][j], d[2][j], d[3][j], d[4][j], d[5][j] };
        float o[6];
        btmul(col, o);
        #pragma unroll
        for (int i = 0; i < 6; i++) tt[i][j] = o[i];
    }
    float* Vp = V + (size_t)ci * T + n;
    size_t ps = (size_t)K * T;
    #pragma unroll
    for (int i = 0; i < 6; i++) {
        float o[6];
        btmul(tt[i], o);
        #pragma unroll
        for (int j = 0; j < 6; j++)
            Vp[(size_t)(i * 6 + j) * ps] = o[j];
    }
}

// --- 36 batched GEMMs, 64co x 128n, 8x4/thread, register double-buffered ---
__global__ __launch_bounds__(256) void wino_gemm(
    const float* __restrict__ U, const float* __restrict__ V,
    float* __restrict__ M, int K, int Co, int T)
{
    const int xi = blockIdx.z;
    const int nb = blockIdx.x * 128;
    const int cb = blockIdx.y * 64;
    const float* Up = U + (size_t)xi * K * Co;
    const float* Vp = V + (size_t)xi * K * T;
    float*       Mp = M + (size_t)xi * Co * T;

    __shared__ __align__(16) float Us[16][64];
    __shared__ __align__(16) float Vs[16][128];

    const int t  = threadIdx.x;
    const int tn = (t & 31) * 4;
    const int tc = (t >> 5) * 8;

    const int ukk = (t * 4) >> 6, ucc = (t * 4) & 63;
    const int vkk = (t * 8) >> 7, vnn = (t * 8) & 127;

    float acc[8][4];
    #pragma unroll
    for (int i = 0; i < 8; i++)
        #pragma unroll
        for (int j = 0; j < 4; j++) acc[i][j] = 0.f;

    float4 ru, rv0, rv1;
    ru  = *(const float4*)&Up[(size_t)ukk * Co + cb + ucc];
    rv0 = *(const float4*)&Vp[(size_t)vkk * T + nb + vnn];
    rv1 = *(const float4*)&Vp[(size_t)vkk * T + nb + vnn + 4];

    const int nChunks = K >> 4;
    for (int c = 0; c < nChunks; c++) {
        if (c > 0) __syncthreads();
        *(float4*)&Us[ukk][ucc]     = ru;
        *(float4*)&Vs[vkk][vnn]     = rv0;
        *(float4*)&Vs[vkk][vnn + 4] = rv1;
        __syncthreads();
        if (c + 1 < nChunks) {
            int k0 = (c + 1) * 16;
            ru  = *(const float4*)&Up[(size_t)(k0 + ukk) * Co + cb + ucc];
            rv0 = *(const float4*)&Vp[(size_t)(k0 + vkk) * T + nb + vnn];
            rv1 = *(const float4*)&Vp[(size_t)(k0 + vkk) * T + nb + vnn + 4];
        }

        #pragma unroll
        for (int k = 0; k < 16; k++) {
            float a[8], bl[4];
            *(float4*)&a[0] = *(const float4*)&Us[k][tc];
            *(float4*)&a[4] = *(const float4*)&Us[k][tc + 4];
            *(float4*)&bl[0] = *(const float4*)&Vs[k][tn];
            #pragma unroll
            for (int i = 0; i < 8; i++)
                #pragma unroll
                for (int j = 0; j < 4; j++)
                    acc[i][j] = fmaf(a[i], bl[j], acc[i][j]);
        }
    }

    #pragma unroll
    for (int i = 0; i < 8; i++)
        *(float4*)&Mp[(size_t)(cb + tc + i) * T + nb + tn] =
            make_float4(acc[i][0], acc[i][1], acc[i][2], acc[i][3]);
}

__device__ __forceinline__ void atmul(const float m[6], float y[4]) {
    y[0] = m[0] + m[1] + m[2] + m[3] + m[4];
    y[1] = m[1] - m[2] + 2.f * m[3] - 2.f * m[4];
    y[2] = m[1] + m[2] + 4.f * m[3] + 4.f * m[4];
    y[3] = m[1] - m[2] + 8.f * m[3] - 8.f * m[4] + m[5];
}

// --- output transform + block-reduced BN partial (1 per block) -------------
// Grid = Co*T/256; T % 256 == 0 so each block covers ONE co.
__global__ __launch_bounds__(256) void wino_outtrans(
    const float* __restrict__ M, float* __restrict__ out,
    float2* __restrict__ part, int Co, int H, int W, int tilesW, int T)
{
    int idx = blockIdx.x * 256 + threadIdx.x;
    int n  = idx % T;
    int co = idx / T;

    int tilesH = H >> 2;
    int tpb = tilesW * tilesH;
    int b  = n / tpb;
    int r  = n - b * tpb;
    int th = r / tilesW;
    int tw = r - th * tilesW;

    float m[6][6];
    const float* Mp = M + (size_t)co * T + n;
    size_t ps = (size_t)Co * T;
    #pragma unroll
    for (int i = 0; i < 6; i++)
        #pragma unroll
        for (int j = 0; j < 6; j++)
            m[i][j] = Mp[(size_t)(i * 6 + j) * ps];

    float s[4][6];
    #pragma unroll
    for (int j = 0; j < 6; j++) {
        float col[6] = { m[0][j], m[1][j], m[2][j], m[3][j], m[4][j], m[5][j] };
        float o[4];
        atmul(col, o);
        #pragma unroll
        for (int i = 0; i < 4; i++) s[i][j] = o[i];
    }

    float sum = 0.f, sq = 0.f;
    float* op = out + (((size_t)b * Co + co) * H + th * 4) * W + tw * 4;
    #pragma unroll
    for (int i = 0; i < 4; i++) {
        float o[4];
        atmul(s[i], o);
        op[i * W + 0] = o[0];
        op[i * W + 1] = o[1];
        op[i * W + 2] = o[2];
        op[i * W + 3] = o[3];
        #pragma unroll
        for (int j = 0; j < 4; j++) { sum += o[j]; sq = fmaf(o[j], o[j], sq); }
    }

    #pragma unroll
    for (int off = 16; off > 0; off >>= 1) {
        sum += __shfl_xor_sync(0xffffffffu, sum, off);
        sq  += __shfl_xor_sync(0xffffffffu, sq,  off);
    }
    __shared__ float2 red[8];
    if ((threadIdx.x & 31) == 0) red[threadIdx.x >> 5] = make_float2(sum, sq);
    __syncthreads();
    if (threadIdx.x == 0) {
        float ts = 0.f, tq = 0.f;
        #pragma unroll
        for (int i = 0; i < 8; i++) { ts += red[i].x; tq += red[i].y; }
        part[blockIdx.x] = make_float2(ts, tq);
    }
}

// --- finalize BN stats from partials (for the 1x1 heads) -------------------
__global__ void bn_finalize(const float2* __restrict__ part, float* __restrict__ stats,
                            int C, int nparts, float invN)
{
    int c = threadIdx.x;
    if (c >= C) return;
    float s = 0.f, sq = 0.f;
    for (int j = 0; j < nparts; j++) {
        float2 v = part[c * nparts + j];
        s += v.x; sq += v.y;
    }
    float m   = s * invN;
    float var = sq * invN - m * m;
    stats[c]     = m;
    stats[C + c] = rsqrtf(var + 1e-5f);
}

// ---------------------------------------------------------------------------
// fused concat assembly (copy + gridsample + coords)
// ---------------------------------------------------------------------------
__device__ __forceinline__ float gs_sample(const float* __restrict__ ip,
                                           float gx, float gy, int H, int W)
{
    float x = (gx + 1.f) * (W * 0.5f) - 0.5f;
    float y = (gy + 1.f) * (H * 0.5f) - 0.5f;
    float x0f = floorf(x), y0f = floorf(y);
    float wx = x - x0f, wy = y - y0f;
    int x0 = (int)x0f, y0 = (int)y0f;
    auto samp = [&](int yi, int xi) -> float {
        bool valid = (xi >= 0) && (xi < W) && (yi >= 0) && (yi < H);
        int yc = min(max(yi, 0), H - 1);
        int xc = min(max(xi, 0), W - 1);
        return valid ? ip[yc * W + xc] : 0.f;
    };
    return samp(y0,     x0    ) * (1.f - wx) * (1.f - wy)
         + samp(y0,     x0 + 1) * wx         * (1.f - wy)
         + samp(y0 + 1, x0    ) * (1.f - wx) * wy
         + samp(y0 + 1, x0 + 1) * wx         * wy;
}

__global__ void concat_coarse(const float* __restrict__ f0c, const float* __restrict__ f1c,
                              const float* __restrict__ warp, float* __restrict__ dst)
{
    const int HW = 4096;
    int idx = blockIdx.x * blockDim.x + threadIdx.x;
    if (idx >= 4 * 130 * HW) return;
    int p = idx % HW;
    int c = (idx / HW) % 130;
    int b = idx / (HW * 130);

    float v;
    if (c < 64) {
        v = f0c[((size_t)b * 64 + c) * HW + p];
    } else if (c < 128) {
        float gx = warp[(b * 2 + 0) * HW + p];
        float gy = warp[(b * 2 + 1) * HW + p];
        v = gs_sample(f1c + ((size_t)b * 64 + (c - 64)) * HW, gx, gy, 64, 64);
    } else {
        v = warp[(b * 2 + (c - 128)) * HW + p];
    }
    dst[((size_t)b * 130 + c) * HW + p] = v;
}

__global__ void concat_fine(const float* __restrict__ f0f, const float* __restrict__ f1f,
                            const float* __restrict__ up, float* __restrict__ dst)
{
    const int HW = 16384;
    int idx = blockIdx.x * blockDim.x + threadIdx.x;
    if (idx >= 4 * 50 * HW) return;
    int p = idx % HW;
    int c = (idx / HW) % 50;
    int b = idx / (HW * 50);

    float v;
    if (c < 24) {
        v = f0f[((size_t)b * 24 + c) * HW + p];
    } else if (c < 48) {
        float gx = up[((size_t)b * 3 + 0) * HW + p];
        float gy = up[((size_t)b * 3 + 1) * HW + p];
        v = gs_sample(f1f + ((size_t)b * 24 + (c - 24)) * HW, gx, gy, 128, 128);
    } else {
        v = up[((size_t)b * 3 + (c - 48)) * HW + p];
    }
    dst[((size_t)b * 50 + c) * HW + p] = v;
}

// ---------------------------------------------------------------------------
__global__ void upsample2x_kernel(const float* __restrict__ src, float* __restrict__ dst,
                                  int B_, int C, int Hi, int Wi)
{
    int Ho = Hi * 2, Wo = Wi * 2;
    int idx = blockIdx.x * blockDim.x + threadIdx.x;
    if (idx >= B_ * C * Ho * Wo) return;
    int wo = idx % Wo;
    int ho = (idx / Wo) % Ho;
    int bc = idx / (Wo * Ho);

    float sy = ho * 0.5f - 0.25f;
    float sx = wo * 0.5f - 0.25f;
    float fy = sy - floorf(sy);
    float fx = sx - floorf(sx);
    int y0 = (int)floorf(sy), x0 = (int)floorf(sx);
    int y0c = min(max(y0, 0), Hi - 1), y1c = min(max(y0 + 1, 0), Hi - 1);
    int x0c = min(max(x0, 0), Wi - 1), x1c = min(max(x0 + 1, 0), Wi - 1);

    const float* sp = src + bc * Hi * Wi;
    float v = sp[y0c * Wi + x0c] * (1.f - fy) * (1.f - fx)
            + sp[y0c * Wi + x1c] * (1.f - fy) * fx
            + sp[y1c * Wi + x0c] * fy * (1.f - fx)
            + sp[y1c * Wi + x1c] * fy * fx;
    dst[idx] = v;
}

// 1x1 conv to 3 ch + bias + base add, BN+ReLU fold on x via stats
__global__ void conv1x1_3_kernel(
    const float* __restrict__ x, const float* __restrict__ stats,
    const float* __restrict__ w5, const float* __restrict__ b5,
    const float* __restrict__ base, int baseC, int baseStrideB,
    float* __restrict__ out, int Cin, int HW, int B_)
{
    int idx = blockIdx.x * blockDim.x + threadIdx.x;
    if (idx >= B_ * HW) return;
    int b = idx / HW, p = idx - b * HW;

    float a0 = 0.f, a1 = 0.f, a2 = 0.f;
    const float* xp = x + (size_t)b * Cin * HW + p;
    for (int ci = 0; ci < Cin; ci++) {
        float v = xp[(size_t)ci * HW];
        v = fmaxf((v - __ldg(&stats[ci])) * __ldg(&stats[Cin + ci]), 0.f);
        a0 = fmaf(v, __ldg(&w5[ci]),            a0);
        a1 = fmaf(v, __ldg(&w5[Cin + ci]),      a1);
        a2 = fmaf(v, __ldg(&w5[2 * Cin + ci]),  a2);
    }
    float b0v = base[b * baseStrideB + p];
    float b1v = base[b * baseStrideB + HW + p];
    float b2v = (baseC > 2) ? base[b * baseStrideB + 2 * HW + p] : 0.f;

    out[(size_t)b * 3 * HW + p]           = a0 + __ldg(&b5[0]) + b0v;
    out[(size_t)b * 3 * HW + HW + p]      = a1 + __ldg(&b5[1]) + b1v;
    out[(size_t)b * 3 * HW + 2 * HW + p]  = a2 + __ldg(&b5[2]) + b2v;
}

// ---------------------------------------------------------------------------
// host-side helper: one Winograd F(4,3) conv layer (+ fused BN handling)
// ---------------------------------------------------------------------------
static void wino_layer(const float* x, const float* Ubase, const float2* partIn,
                       float* out, float* V, float* M, float2* partOut,
                       int Cin, int K, int Co, int H, int W)
{
    int tilesW = W >> 2, tilesH = H >> 2;
    int T = 4 * tilesW * tilesH;
    float invN = 1.f / (float)(T * 16);

    wino_intrans<<<K * T / 256, 256>>>(x, partIn, T / 256, invN, V,
                                       Cin, K, H, W, tilesW, T);
    dim3 gg(T / 128, Co / 64, 36);
    wino_gemm<<<gg, 256>>>(Ubase, V, M, K, Co, T);
    wino_outtrans<<<Co * T / 256, 256>>>(M, out, partOut, Co, H, W, tilesW, T);
}

// ---------------------------------------------------------------------------
extern "C" void kernel_launch(void* const* d_in, const int* in_sizes, int n_in,
                              void* d_out, int out_size)
{
    const float* f0c = (const float*)d_in[0];
    const float* f1c = (const float*)d_in[1];
    const float* f0f = (const float*)d_in[2];
    const float* f1f = (const float*)d_in[3];
    const float* cw1 = (const float*)d_in[4];
    const float* cw2 = (const float*)d_in[5];
    const float* cw3 = (const float*)d_in[6];
    const float* cw4 = (const float*)d_in[7];
    const float* cw5 = (const float*)d_in[8];
    const float* cb5 = (const float*)d_in[9];
    const float* fw1 = (const float*)d_in[10];
    const float* fw2 = (const float*)d_in[11];
    const float* fw3 = (const float*)d_in[12];
    const float* fw4 = (const float*)d_in[13];
    const float* fw5 = (const float*)d_in[14];
    const float* fb5 = (const float*)d_in[15];

    float *A, *Bb, *V, *M, *U, *warp, *stats;
    float2* part;
    cudaGetSymbolAddress((void**)&A,     g_bufA);
    cudaGetSymbolAddress((void**)&Bb,    g_bufB);
    cudaGetSymbolAddress((void**)&V,     g_V);
    cudaGetSymbolAddress((void**)&M,     g_M);
    cudaGetSymbolAddress((void**)&U,     g_U);
    cudaGetSymbolAddress((void**)&part,  g_bnpart);
    cudaGetSymbolAddress((void**)&warp,  g_warp);
    cudaGetSymbolAddress((void**)&stats, g_stats);

    float* outC = (float*)d_out;                 // (4,3,64,64)
    float* outF = outC + 4 * 3 * 64 * 64;        // (4,3,128,128)

    const int HWc = 64 * 64, HWf = 128 * 128;

    // ---- all weight transforms up front (one kernel) ----
    wino_wtrans_all<<<(249856 + 255) / 256, 256>>>(cw1, cw2, cw3, cw4,
                                                   fw1, fw2, fw3, fw4, U);

    // ---- coarse stage ----
    corr_kernel<<<512, 128>>>(f0c, f1c, warp);

    concat_coarse<<<(4 * 130 * HWc + 255) / 256, 256>>>(f0c, f1c, warp, A);

    wino_layer(A,  U + UO1, nullptr, Bb, V, M, part, 130, 144, 256, 64, 64);
    wino_layer(Bb, U + UO2, part,    A,  V, M, part, 256, 256, 256, 64, 64);
    wino_layer(A,  U + UO3, part,    Bb, V, M, part, 256, 256, 256, 64, 64);
    wino_layer(Bb, U + UO4, part,    A,  V, M, part, 256, 256, 256, 64, 64);

    bn_finalize<<<1, 256>>>(part, stats, 256, 4, 1.f / 16384.f);
    conv1x1_3_kernel<<<(4 * HWc + 127) / 128, 128>>>(
        A, stats, cw5, cb5, warp, 2, 2 * HWc, outC, 256, HWc, 4);

    // ---- fine stage ----
    upsample2x_kernel<<<(4 * 3 * HWf + 255) / 256, 256>>>(outC, outF, 4, 3, 64, 64);

    concat_fine<<<(4 * 50 * HWf + 255) / 256, 256>>>(f0f, f1f, outF, Bb);

    wino_layer(Bb, U + UF1, nullptr, A,  V, M, part, 50, 64, 64, 128, 128);
    wino_layer(A,  U + UF2, part,    Bb, V, M, part, 64, 64, 64, 128, 128);
    wino_layer(Bb, U + UF3, part,    A,  V, M, part, 64, 64, 64, 128, 128);
    wino_layer(A,  U + UF4, part,    Bb, V, M, part, 64, 64, 64, 128, 128);

    bn_finalize<<<1, 256>>>(part, stats, 64, 16, 1.f / 65536.f);
    conv1x1_3_kernel<<<(4 * HWf + 127) / 128, 128>>>(
        Bb, stats, fw5, fb5, outF, 3, 3 * HWf, outF, 64, HWf, 4);
}

// round 14
// speedup vs baseline: 1.0661x; 1.0023x over previous
#include <cuda_runtime.h>
#include <cuda_bf16.h>
#include <math.h>

typedef unsigned long long u64;

__device__ __forceinline__ u64 pack2(float lo, float hi) {
    u64 r; asm("mov.b64 %0,{%1,%2};" : "=l"(r) : "f"(lo), "f"(hi)); return r;
}
__device__ __forceinline__ void unpack2(u64 v, float& lo, float& hi) {
    asm("mov.b64 {%0,%1},%2;" : "=f"(lo), "=f"(hi) : "l"(v));
}
__device__ __forceinline__ u64 fma2(u64 a, u64 b, u64 c) {
    u64 d; asm("fma.rn.f32x2 %0,%1,%2,%3;" : "=l"(d) : "l"(a), "l"(b), "l"(c)); return d;
}

// ---------------- scratch (device globals; no allocations) ----------------
__device__ float g_bufA[4u * 256u * 64u * 64u];     // 16.8 MB
__device__ float g_bufB[4u * 256u * 64u * 64u];     // 16.8 MB
__device__ float g_V[16u * 256u * 4096u];           // 67 MB (Winograd V)
__device__ float g_M[16u * 256u * 4096u];           // 67 MB (Winograd M)
__device__ float g_U[9u * 1024u * 1024u];           // 36 MB (all layers' U)
__device__ float2 g_bnpart[8192];                   // per-block BN partials
__device__ float g_warp[4 * 2 * 64 * 64];
__device__ float g_stats[1024];                     // [mean(C) | rstd(C)]

// U offsets per layer (floats)
#define UO1  0u
#define UO2  1327104u      // + 36*144*256
#define UO3  3686400u      // + 36*256*256
#define UO4  6045696u
#define UF1  8404992u
#define UF2  8552448u      // + 36*64*64
#define UF3  8699904u
#define UF4  8847360u

// ---------------------------------------------------------------------------
// Kernel 1: fused correlation + softmax + expected grid position
// ---------------------------------------------------------------------------
__global__ __launch_bounds__(128) void corr_kernel(
    const float* __restrict__ f0, const float* __restrict__ f1,
    float* __restrict__ warp)
{
    const int b  = blockIdx.x >> 7;
    const int p0 = (blockIdx.x & 127) * 32;

    __shared__ __align__(16) float f0_s[64][32];
    __shared__ __align__(16) float f1_sc[64 * 128];
    __shared__ float m_s[32], l_s[32], sx_s[32], sy_s[32];

    const int t    = threadIdx.x;
    const int tx   = t & 15;
    const int ty   = t >> 4;
    const int q    = t >> 2;
    const int quad = t & 3;

    for (int i = t; i < 64 * 32; i += 128) {
        int p = i & 31, c = i >> 5;
        f0_s[c][p] = f0[(b * 64 + c) * 4096 + p0 + p];
    }
    if (t < 32) { m_s[t] = -1e30f; l_s[t] = 0.f; sx_s[t] = 0.f; sy_s[t] = 0.f; }
    __syncthreads();

    for (int j0 = 0; j0 < 4096; j0 += 128) {
        for (int i = t; i < 64 * 128; i += 128) {
            int j = i & 127, c = i >> 7;
            f1_sc[c * 128 + j] = f1[(b * 64 + c) * 4096 + j0 + j];
        }
        __syncthreads();

        u64 acc2[4][4];
        #pragma unroll
        for (int i = 0; i < 4; i++)
            #pragma unroll
            for (int jp = 0; jp < 4; jp++) acc2[i][jp] = 0ull;

        #pragma unroll 16
        for (int c = 0; c < 64; c++) {
            float4 a0 = *(const float4*)&f0_s[c][ty * 4];
            u64 ap[4] = { pack2(a0.x, a0.x), pack2(a0.y, a0.y),
                          pack2(a0.z, a0.z), pack2(a0.w, a0.w) };
            const u64* bp = (const u64*)&f1_sc[c * 128 + tx * 8];
            u64 b0 = bp[0], b1 = bp[1], b2 = bp[2], b3 = bp[3];
            #pragma unroll
            for (int i = 0; i < 4; i++) {
                acc2[i][0] = fma2(ap[i], b0, acc2[i][0]);
                acc2[i][1] = fma2(ap[i], b1, acc2[i][1]);
                acc2[i][2] = fma2(ap[i], b2, acc2[i][2]);
                acc2[i][3] = fma2(ap[i], b3, acc2[i][3]);
            }
        }
        __syncthreads();

        #pragma unroll
        for (int i = 0; i < 4; i++)
            #pragma unroll
            for (int jp = 0; jp < 4; jp++) {
                float lo, hi; unpack2(acc2[i][jp], lo, hi);
                f1_sc[(ty * 4 + i) * 132 + tx * 8 + 2 * jp]     = lo * 0.125f;
                f1_sc[(ty * 4 + i) * 132 + tx * 8 + 2 * jp + 1] = hi * 0.125f;
            }
        __syncthreads();

        float m_old = m_s[q];
        float sc[32];
        float tm = -1e30f;
        #pragma unroll
        for (int i = 0; i < 32; i++) {
            sc[i] = f1_sc[q * 132 + quad + 4 * i];
            tm = fmaxf(tm, sc[i]);
        }
        tm = fmaxf(tm, __shfl_xor_sync(0xffffffffu, tm, 1));
        tm = fmaxf(tm, __shfl_xor_sync(0xffffffffu, tm, 2));
        float nm = fmaxf(m_old, tm);

        float le = 0.f, lx = 0.f, ly = 0.f;
        #pragma unroll
        for (int i = 0; i < 32; i++) {
            int j   = j0 + quad + 4 * i;
            float e = __expf(sc[i] - nm);
            float gx = (float)((j & 63) * 2 + 1) * (1.f / 64.f) - 1.f;
            float gy = (float)((j >> 6) * 2 + 1) * (1.f / 64.f) - 1.f;
            le += e;
            lx = fmaf(e, gx, lx);
            ly = fmaf(e, gy, ly);
        }
        le += __shfl_xor_sync(0xffffffffu, le, 1);
        le += __shfl_xor_sync(0xffffffffu, le, 2);
        lx += __shfl_xor_sync(0xffffffffu, lx, 1);
        lx += __shfl_xor_sync(0xffffffffu, lx, 2);
        ly += __shfl_xor_sync(0xffffffffu, ly, 1);
        ly += __shfl_xor_sync(0xffffffffu, ly, 2);

        if (quad == 0) {
            float s = __expf(m_old - nm);
            l_s[q]  = l_s[q]  * s + le;
            sx_s[q] = sx_s[q] * s + lx;
            sy_s[q] = sy_s[q] * s + ly;
            m_s[q]  = nm;
        }
        __syncthreads();
    }

    if (t < 32) {
        float inv = 1.f / l_s[t];
        warp[(b * 2 + 0) * 4096 + p0 + t] = sx_s[t] * inv;
        warp[(b * 2 + 1) * 4096 + p0 + t] = sy_s[t] * inv;
    }
}

// ===========================================================================
// Winograd F(4x4, 3x3)
// ===========================================================================

__device__ __forceinline__ void gmul(float a0, float a1, float a2, float o[6]) {
    o[0] = 0.25f * a0;
    o[1] = (-1.f / 6.f) * (a0 + a1 + a2);
    o[2] = (1.f / 6.f) * (-a0 + a1 - a2);
    o[3] = (1.f / 24.f) * a0 + (1.f / 12.f) * a1 + (1.f / 6.f) * a2;
    o[4] = (1.f / 24.f) * a0 - (1.f / 12.f) * a1 + (1.f / 6.f) * a2;
    o[5] = a2;
}

// --- one fused weight transform for ALL 8 layers ---------------------------
__global__ void wino_wtrans_all(
    const float* __restrict__ cw1, const float* __restrict__ cw2,
    const float* __restrict__ cw3, const float* __restrict__ cw4,
    const float* __restrict__ fw1, const float* __restrict__ fw2,
    const float* __restrict__ fw3, const float* __restrict__ fw4,
    float* __restrict__ U)
{
    int idx = blockIdx.x * blockDim.x + threadIdx.x;
    const float* w; int Cin, K, Co; unsigned base;
    if      (idx < 36864)  { w = cw1; Cin = 130; K = 144; Co = 256; base = UO1; }
    else if (idx < 102400) { w = cw2; Cin = 256; K = 256; Co = 256; base = UO2; idx -= 36864; }
    else if (idx < 167936) { w = cw3; Cin = 256; K = 256; Co = 256; base = UO3; idx -= 102400; }
    else if (idx < 233472) { w = cw4; Cin = 256; K = 256; Co = 256; base = UO4; idx -= 167936; }
    else if (idx < 237568) { w = fw1; Cin = 50;  K = 64;  Co = 64;  base = UF1; idx -= 233472; }
    else if (idx < 241664) { w = fw2; Cin = 64;  K = 64;  Co = 64;  base = UF2; idx -= 237568; }
    else if (idx < 245760) { w = fw3; Cin = 64;  K = 64;  Co = 64;  base = UF3; idx -= 241664; }
    else if (idx < 249856) { w = fw4; Cin = 64;  K = 64;  Co = 64;  base = UF4; idx -= 245760; }
    else return;

    int co = idx % Co;
    int ci = idx / Co;

    float g[3][3];
    #pragma unroll
    for (int i = 0; i < 3; i++)
        #pragma unroll
        for (int j = 0; j < 3; j++)
            g[i][j] = (ci < Cin) ? w[(co * Cin + ci) * 9 + i * 3 + j] : 0.f;

    float u[6][3];
    #pragma unroll
    for (int j = 0; j < 3; j++) {
        float col[6];
        gmul(g[0][j], g[1][j], g[2][j], col);
        #pragma unroll
        for (int i = 0; i < 6; i++) u[i][j] = col[i];
    }
    #pragma unroll
    for (int i = 0; i < 6; i++) {
        float row[6];
        gmul(u[i][0], u[i][1], u[i][2], row);
        #pragma unroll
        for (int j = 0; j < 6; j++)
            U[base + ((size_t)(i * 6 + j) * K + ci) * Co + co] = row[j];
    }
}

__device__ __forceinline__ void btmul(const float x[6], float y[6]) {
    y[0] =  4.f * x[0] - 5.f * x[2] + x[4];
    y[1] = -4.f * x[1] - 4.f * x[2] + x[3] + x[4];
    y[2] =  4.f * x[1] - 4.f * x[2] - x[3] + x[4];
    y[3] = -2.f * x[1] -       x[2] + 2.f * x[3] + x[4];
    y[4] =  2.f * x[1] -       x[2] - 2.f * x[3] + x[4];
    y[5] =  4.f * x[1] - 5.f * x[3] + x[5];
}

// --- input transform: V = B^T d B; BN fold computed inline from partials ---
// Grid is exactly K*T/256 blocks; T % 256 == 0 so each block touches ONE ci.
__global__ __launch_bounds__(256) void wino_intrans(
    const float* __restrict__ in, const float2* __restrict__ part,
    int nparts, float invN, float* __restrict__ V,
    int Cin, int K, int H, int W, int tilesW, int T)
{
    int idx = blockIdx.x * 256 + threadIdx.x;
    int n  = idx % T;
    int ci = idx / T;

    __shared__ float s_mu, s_rs;
    const bool hasBN = (part != nullptr);
    if (hasBN) {
        if (threadIdx.x == 0) {
            int c0 = (blockIdx.x * 256) / T;
            if (c0 < Cin) {
                float s = 0.f, sq = 0.f;
                for (int j = 0; j < nparts; j++) {
                    float2 v = part[c0 * nparts + j];
                    s += v.x; sq += v.y;
                }
                float m   = s * invN;
                float var = sq * invN - m * m;
                s_mu = m;
                s_rs = rsqrtf(var + 1e-5f);
            } else { s_mu = 0.f; s_rs = 1.f; }
        }
        __syncthreads();
    }

    int tilesH = H >> 2;
    int tpb = tilesW * tilesH;
    int b  = n / tpb;
    int r  = n - b * tpb;
    int th = r / tilesW;
    int tw = r - th * tilesW;

    float d[6][6];
    if (ci < Cin) {
        const float* ip = in + ((size_t)b * Cin + ci) * H * W;
        float mu = hasBN ? s_mu : 0.f;
        float rs = hasBN ? s_rs : 0.f;
        int h0 = th * 4 - 1, w0 = tw * 4 - 1;
        #pragma unroll
        for (int i = 0; i < 6; i++) {
            int h = h0 + i;
            #pragma unroll
            for (int j = 0; j < 6; j++) {
                int w = w0 + j;
                float v = 0.f;
                if ((unsigned)h < (unsigned)H && (unsigned)w < (unsigned)W) {
                    v = ip[h * W + w];
                    if (hasBN) v = fmaxf((v - mu) * rs, 0.f);
                }
                d[i][j] = v;
            }
        }
    } else {
        #pragma unroll
        for (int i = 0; i < 6; i++)
            #pragma unroll
            for (int j = 0; j < 6; j++) d[i][j] = 0.f;
    }

    float tt[6][6];
    #pragma unroll
    for (int j = 0; j < 6; j++) {
        float col[6] = { d[0][j], d[1][j], d[2][j], d[3][j], d[4][j], d[5][j] };
        float o[6];
        btmul(col, o);
        #pragma unroll
        for (int i = 0; i < 6; i++) tt[i][j] = o[i];
    }
    float* Vp = V + (size_t)ci * T + n;
    size_t ps = (size_t)K * T;
    #pragma unroll
    for (int i = 0; i < 6; i++) {
        float o[6];
        btmul(tt[i], o);
        #pragma unroll
        for (int j = 0; j < 6; j++)
            Vp[(size_t)(i * 6 + j) * ps] = o[j];
    }
}

// --- 36 batched GEMMs, 64co x 128n, 8x4/thread, smem double-buffered -------
// One __syncthreads per K-chunk; LDG prefetch overlaps compute.
__global__ __launch_bounds__(256) void wino_gemm(
    const float* __restrict__ U, const float* __restrict__ V,
    float* __restrict__ M, int K, int Co, int T)
{
    const int xi = blockIdx.z;
    const int nb = blockIdx.x * 128;
    const int cb = blockIdx.y * 64;
    const float* Up = U + (size_t)xi * K * Co;
    const float* Vp = V + (size_t)xi * K * T;
    float*       Mp = M + (size_t)xi * Co * T;

    __shared__ __align__(16) float Us[2][16][64];
    __shared__ __align__(16) float Vs[2][16][128];

    const int t  = threadIdx.x;
    const int tn = (t & 31) * 4;
    const int tc = (t >> 5) * 8;

    const int ukk = (t * 4) >> 6, ucc = (t * 4) & 63;
    const int vkk = (t * 8) >> 7, vnn = (t * 8) & 127;

    float acc[8][4];
    #pragma unroll
    for (int i = 0; i < 8; i++)
        #pragma unroll
        for (int j = 0; j < 4; j++) acc[i][j] = 0.f;

    float4 ru, rv0, rv1;
    // prologue: chunk 0 -> buffer 0
    ru  = *(const float4*)&Up[(size_t)ukk * Co + cb + ucc];
    rv0 = *(const float4*)&Vp[(size_t)vkk * T + nb + vnn];
    rv1 = *(const float4*)&Vp[(size_t)vkk * T + nb + vnn + 4];
    *(float4*)&Us[0][ukk][ucc]     = ru;
    *(float4*)&Vs[0][vkk][vnn]     = rv0;
    *(float4*)&Vs[0][vkk][vnn + 4] = rv1;
    __syncthreads();

    const int nChunks = K >> 4;
    for (int c = 0; c < nChunks; c++) {
        const int cur = c & 1;
        if (c + 1 < nChunks) {
            int k0 = (c + 1) * 16;
            ru  = *(const float4*)&Up[(size_t)(k0 + ukk) * Co + cb + ucc];
            rv0 = *(const float4*)&Vp[(size_t)(k0 + vkk) * T + nb + vnn];
            rv1 = *(const float4*)&Vp[(size_t)(k0 + vkk) * T + nb + vnn + 4];
        }

        const float (*us)[64]  = Us[cur];
        const float (*vs)[128] = Vs[cur];
        #pragma unroll
        for (int k = 0; k < 16; k++) {
            float a[8], bl[4];
            *(float4*)&a[0] = *(const float4*)&us[k][tc];
            *(float4*)&a[4] = *(const float4*)&us[k][tc + 4];
            *(float4*)&bl[0] = *(const float4*)&vs[k][tn];
            #pragma unroll
            for (int i = 0; i < 8; i++)
                #pragma unroll
                for (int j = 0; j < 4; j++)
                    acc[i][j] = fmaf(a[i], bl[j], acc[i][j]);
        }

        if (c + 1 < nChunks) {
            *(float4*)&Us[cur ^ 1][ukk][ucc]     = ru;
            *(float4*)&Vs[cur ^ 1][vkk][vnn]     = rv0;
            *(float4*)&Vs[cur ^ 1][vkk][vnn + 4] = rv1;
            __syncthreads();
        }
    }

    #pragma unroll
    for (int i = 0; i < 8; i++)
        *(float4*)&Mp[(size_t)(cb + tc + i) * T + nb + tn] =
            make_float4(acc[i][0], acc[i][1], acc[i][2], acc[i][3]);
}

__device__ __forceinline__ void atmul(const float m[6], float y[4]) {
    y[0] = m[0] + m[1] + m[2] + m[3] + m[4];
    y[1] = m[1] - m[2] + 2.f * m[3] - 2.f * m[4];
    y[2] = m[1] + m[2] + 4.f * m[3] + 4.f * m[4];
    y[3] = m[1] - m[2] + 8.f * m[3] - 8.f * m[4] + m[5];
}

// --- output transform + block-reduced BN partial (1 per block) -------------
// Grid = Co*T/256; T % 256 == 0 so each block covers ONE co.
__global__ __launch_bounds__(256) void wino_outtrans(
    const float* __restrict__ M, float* __restrict__ out,
    float2* __restrict__ part, int Co, int H, int W, int tilesW, int T)
{
    int idx = blockIdx.x * 256 + threadIdx.x;
    int n  = idx % T;
    int co = idx / T;

    int tilesH = H >> 2;
    int tpb = tilesW * tilesH;
    int b  = n / tpb;
    int r  = n - b * tpb;
    int th = r / tilesW;
    int tw = r - th * tilesW;

    float m[6][6];
    const float* Mp = M + (size_t)co * T + n;
    size_t ps = (size_t)Co * T;
    #pragma unroll
    for (int i = 0; i < 6; i++)
        #pragma unroll
        for (int j = 0; j < 6; j++)
            m[i][j] = Mp[(size_t)(i * 6 + j) * ps];

    float s[4][6];
    #pragma unroll
    for (int j = 0; j < 6; j++) {
        float col[6] = { m[0][j], m[1][j], m[2][j], m[3][j], m[4][j], m[5][j] };
        float o[4];
        atmul(col, o);
        #pragma unroll
        for (int i = 0; i < 4; i++) s[i][j] = o[i];
    }

    float sum = 0.f, sq = 0.f;
    float* op = out + (((size_t)b * Co + co) * H + th * 4) * W + tw * 4;
    #pragma unroll
    for (int i = 0; i < 4; i++) {
        float o[4];
        atmul(s[i], o);
        op[i * W + 0] = o[0];
        op[i * W + 1] = o[1];
        op[i * W + 2] = o[2];
        op[i * W + 3] = o[3];
        #pragma unroll
        for (int j = 0; j < 4; j++) { sum += o[j]; sq = fmaf(o[j], o[j], sq); }
    }

    #pragma unroll
    for (int off = 16; off > 0; off >>= 1) {
        sum += __shfl_xor_sync(0xffffffffu, sum, off);
        sq  += __shfl_xor_sync(0xffffffffu, sq,  off);
    }
    __shared__ float2 red[8];
    if ((threadIdx.x & 31) == 0) red[threadIdx.x >> 5] = make_float2(sum, sq);
    __syncthreads();
    if (threadIdx.x == 0) {
        float ts = 0.f, tq = 0.f;
        #pragma unroll
        for (int i = 0; i < 8; i++) { ts += red[i].x; tq += red[i].y; }
        part[blockIdx.x] = make_float2(ts, tq);
    }
}

// --- finalize BN stats from partials (for the 1x1 heads) -------------------
__global__ void bn_finalize(const float2* __restrict__ part, float* __restrict__ stats,
                            int C, int nparts, float invN)
{
    int c = threadIdx.x;
    if (c >= C) return;
    float s = 0.f, sq = 0.f;
    for (int j = 0; j < nparts; j++) {
        float2 v = part[c * nparts + j];
        s += v.x; sq += v.y;
    }
    float m   = s * invN;
    float var = sq * invN - m * m;
    stats[c]     = m;
    stats[C + c] = rsqrtf(var + 1e-5f);
}

// ---------------------------------------------------------------------------
// fused concat assembly (copy + gridsample + coords)
// ---------------------------------------------------------------------------
__device__ __forceinline__ float gs_sample(const float* __restrict__ ip,
                                           float gx, float gy, int H, int W)
{
    float x = (gx + 1.f) * (W * 0.5f) - 0.5f;
    float y = (gy + 1.f) * (H * 0.5f) - 0.5f;
    float x0f = floorf(x), y0f = floorf(y);
    float wx = x - x0f, wy = y - y0f;
    int x0 = (int)x0f, y0 = (int)y0f;
    auto samp = [&](int yi, int xi) -> float {
        bool valid = (xi >= 0) && (xi < W) && (yi >= 0) && (yi < H);
        int yc = min(max(yi, 0), H - 1);
        int xc = min(max(xi, 0), W - 1);
        return valid ? ip[yc * W + xc] : 0.f;
    };
    return samp(y0,     x0    ) * (1.f - wx) * (1.f - wy)
         + samp(y0,     x0 + 1) * wx         * (1.f - wy)
         + samp(y0 + 1, x0    ) * (1.f - wx) * wy
         + samp(y0 + 1, x0 + 1) * wx         * wy;
}

__global__ void concat_coarse(const float* __restrict__ f0c, const float* __restrict__ f1c,
                              const float* __restrict__ warp, float* __restrict__ dst)
{
    const int HW = 4096;
    int idx = blockIdx.x * blockDim.x + threadIdx.x;
    if (idx >= 4 * 130 * HW) return;
    int p = idx % HW;
    int c = (idx / HW) % 130;
    int b = idx / (HW * 130);

    float v;
    if (c < 64) {
        v = f0c[((size_t)b * 64 + c) * HW + p];
    } else if (c < 128) {
        float gx = warp[(b * 2 + 0) * HW + p];
        float gy = warp[(b * 2 + 1) * HW + p];
        v = gs_sample(f1c + ((size_t)b * 64 + (c - 64)) * HW, gx, gy, 64, 64);
    } else {
        v = warp[(b * 2 + (c - 128)) * HW + p];
    }
    dst[((size_t)b * 130 + c) * HW + p] = v;
}

__global__ void concat_fine(const float* __restrict__ f0f, const float* __restrict__ f1f,
                            const float* __restrict__ up, float* __restrict__ dst)
{
    const int HW = 16384;
    int idx = blockIdx.x * blockDim.x + threadIdx.x;
    if (idx >= 4 * 50 * HW) return;
    int p = idx % HW;
    int c = (idx / HW) % 50;
    int b = idx / (HW * 50);

    float v;
    if (c < 24) {
        v = f0f[((size_t)b * 24 + c) * HW + p];
    } else if (c < 48) {
        float gx = up[((size_t)b * 3 + 0) * HW + p];
        float gy = up[((size_t)b * 3 + 1) * HW + p];
        v = gs_sample(f1f + ((size_t)b * 24 + (c - 24)) * HW, gx, gy, 128, 128);
    } else {
        v = up[((size_t)b * 3 + (c - 48)) * HW + p];
    }
    dst[((size_t)b * 50 + c) * HW + p] = v;
}

// ---------------------------------------------------------------------------
__global__ void upsample2x_kernel(const float* __restrict__ src, float* __restrict__ dst,
                                  int B_, int C, int Hi, int Wi)
{
    int Ho = Hi * 2, Wo = Wi * 2;
    int idx = blockIdx.x * blockDim.x + threadIdx.x;
    if (idx >= B_ * C * Ho * Wo) return;
    int wo = idx % Wo;
    int ho = (idx / Wo) % Ho;
    int bc = idx / (Wo * Ho);

    float sy = ho * 0.5f - 0.25f;
    float sx = wo * 0.5f - 0.25f;
    float fy = sy - floorf(sy);
    float fx = sx - floorf(sx);
    int y0 = (int)floorf(sy), x0 = (int)floorf(sx);
    int y0c = min(max(y0, 0), Hi - 1), y1c = min(max(y0 + 1, 0), Hi - 1);
    int x0c = min(max(x0, 0), Wi - 1), x1c = min(max(x0 + 1, 0), Wi - 1);

    const float* sp = src + bc * Hi * Wi;
    float v = sp[y0c * Wi + x0c] * (1.f - fy) * (1.f - fx)
            + sp[y0c * Wi + x1c] * (1.f - fy) * fx
            + sp[y1c * Wi + x0c] * fy * (1.f - fx)
            + sp[y1c * Wi + x1c] * fy * fx;
    dst[idx] = v;
}

// 1x1 conv to 3 ch + bias + base add, BN+ReLU fold, channel-split for ILP.
// Block: 32 pixels x 8 channel-groups (256 thr). Grid: B*HW/32.
__global__ __launch_bounds__(256) void conv1x1_3_kernel(
    const float* __restrict__ x, const float* __restrict__ stats,
    const float* __restrict__ w5, const float* __restrict__ b5,
    const float* __restrict__ base, int baseC, int baseStrideB,
    float* __restrict__ out, int Cin, int HW, int B_)
{
    const int lane = threadIdx.x & 31;
    const int g    = threadIdx.x >> 5;          // 0..7
    const int pix  = blockIdx.x * 32 + lane;
    const int b = pix / HW, p = pix - b * HW;
    const int cpg = Cin >> 3;
    const int c0  = g * cpg;

    float a0 = 0.f, a1 = 0.f, a2 = 0.f;
    const float* xp = x + ((size_t)b * Cin + c0) * HW + p;
    for (int i = 0; i < cpg; i++) {
        int ci = c0 + i;
        float v = xp[(size_t)i * HW];
        v = fmaxf((v - __ldg(&stats[ci])) * __ldg(&stats[Cin + ci]), 0.f);
        a0 = fmaf(v, __ldg(&w5[ci]),            a0);
        a1 = fmaf(v, __ldg(&w5[Cin + ci]),      a1);
        a2 = fmaf(v, __ldg(&w5[2 * Cin + ci]),  a2);
    }

    __shared__ float r[3][8][32];
    r[0][g][lane] = a0;
    r[1][g][lane] = a1;
    r[2][g][lane] = a2;
    __syncthreads();

    if (g == 0) {
        float s0 = 0.f, s1 = 0.f, s2 = 0.f;
        #pragma unroll
        for (int j = 0; j < 8; j++) {
            s0 += r[0][j][lane];
            s1 += r[1][j][lane];
            s2 += r[2][j][lane];
        }
        float b0v = base[b * baseStrideB + p];
        float b1v = base[b * baseStrideB + HW + p];
        float b2v = (baseC > 2) ? base[b * baseStrideB + 2 * HW + p] : 0.f;

        out[(size_t)b * 3 * HW + p]           = s0 + __ldg(&b5[0]) + b0v;
        out[(size_t)b * 3 * HW + HW + p]      = s1 + __ldg(&b5[1]) + b1v;
        out[(size_t)b * 3 * HW + 2 * HW + p]  = s2 + __ldg(&b5[2]) + b2v;
    }
}

// ---------------------------------------------------------------------------
// host-side helper: one Winograd F(4,3) conv layer (+ fused BN handling)
// ---------------------------------------------------------------------------
static void wino_layer(const float* x, const float* Ubase, const float2* partIn,
                       float* out, float* V, float* M, float2* partOut,
                       int Cin, int K, int Co, int H, int W)
{
    int tilesW = W >> 2, tilesH = H >> 2;
    int T = 4 * tilesW * tilesH;
    float invN = 1.f / (float)(T * 16);

    wino_intrans<<<K * T / 256, 256>>>(x, partIn, T / 256, invN, V,
                                       Cin, K, H, W, tilesW, T);
    dim3 gg(T / 128, Co / 64, 36);
    wino_gemm<<<gg, 256>>>(Ubase, V, M, K, Co, T);
    wino_outtrans<<<Co * T / 256, 256>>>(M, out, partOut, Co, H, W, tilesW, T);
}

// ---------------------------------------------------------------------------
extern "C" void kernel_launch(void* const* d_in, const int* in_sizes, int n_in,
                              void* d_out, int out_size)
{
    const float* f0c = (const float*)d_in[0];
    const float* f1c = (const float*)d_in[1];
    const float* f0f = (const float*)d_in[2];
    const float* f1f = (const float*)d_in[3];
    const float* cw1 = (const float*)d_in[4];
    const float* cw2 = (const float*)d_in[5];
    const float* cw3 = (const float*)d_in[6];
    const float* cw4 = (const float*)d_in[7];
    const float* cw5 = (const float*)d_in[8];
    const float* cb5 = (const float*)d_in[9];
    const float* fw1 = (const float*)d_in[10];
    const float* fw2 = (const float*)d_in[11];
    const float* fw3 = (const float*)d_in[12];
    const float* fw4 = (const float*)d_in[13];
    const float* fw5 = (const float*)d_in[14];
    const float* fb5 = (const float*)d_in[15];

    float *A, *Bb, *V, *M, *U, *warp, *stats;
    float2* part;
    cudaGetSymbolAddress((void**)&A,     g_bufA);
    cudaGetSymbolAddress((void**)&Bb,    g_bufB);
    cudaGetSymbolAddress((void**)&V,     g_V);
    cudaGetSymbolAddress((void**)&M,     g_M);
    cudaGetSymbolAddress((void**)&U,     g_U);
    cudaGetSymbolAddress((void**)&part,  g_bnpart);
    cudaGetSymbolAddress((void**)&warp,  g_warp);
    cudaGetSymbolAddress((void**)&stats, g_stats);

    float* outC = (float*)d_out;                 // (4,3,64,64)
    float* outF = outC + 4 * 3 * 64 * 64;        // (4,3,128,128)

    const int HWc = 64 * 64, HWf = 128 * 128;

    // ---- all weight transforms up front (one kernel) ----
    wino_wtrans_all<<<(249856 + 255) / 256, 256>>>(cw1, cw2, cw3, cw4,
                                                   fw1, fw2, fw3, fw4, U);

    // ---- coarse stage ----
    corr_kernel<<<512, 128>>>(f0c, f1c, warp);

    concat_coarse<<<(4 * 130 * HWc + 255) / 256, 256>>>(f0c, f1c, warp, A);

    wino_layer(A,  U + UO1, nullptr, Bb, V, M, part, 130, 144, 256, 64, 64);
    wino_layer(Bb, U + UO2, part,    A,  V, M, part, 256, 256, 256, 64, 64);
    wino_layer(A,  U + UO3, part,    Bb, V, M, part, 256, 256, 256, 64, 64);
    wino_layer(Bb, U + UO4, part,    A,  V, M, part, 256, 256, 256, 64, 64);

    bn_finalize<<<1, 256>>>(part, stats, 256, 4, 1.f / 16384.f);
    conv1x1_3_kernel<<<4 * HWc / 32, 256>>>(
        A, stats, cw5, cb5, warp, 2, 2 * HWc, outC, 256, HWc, 4);

    // ---- fine stage ----
    upsample2x_kernel<<<(4 * 3 * HWf + 255) / 256, 256>>>(outC, outF, 4, 3, 64, 64);

    concat_fine<<<(4 * 50 * HWf + 255) / 256, 256>>>(f0f, f1f, outF, Bb);

    wino_layer(Bb, U + UF1, nullptr, A,  V, M, part, 50, 64, 64, 128, 128);
    wino_layer(A,  U + UF2, part,    Bb, V, M, part, 64, 64, 64, 128, 128);
    wino_layer(Bb, U + UF3, part,    A,  V, M, part, 64, 64, 64, 128, 128);
    wino_layer(A,  U + UF4, part,    Bb, V, M, part, 64, 64, 64, 128, 128);

    bn_finalize<<<1, 256>>>(part, stats, 64, 16, 1.f / 65536.f);
    conv1x1_3_kernel<<<4 * HWf / 32, 256>>>(
        Bb, stats, fw5, fb5, outF, 3, 3 * HWf, outF, 64, HWf, 4);
}

// round 15
// speedup vs baseline: 1.1712x; 1.0986x over previous
#include <cuda_runtime.h>
#include <cuda_bf16.h>
#include <math.h>

typedef unsigned long long u64;

__device__ __forceinline__ u64 pack2(float lo, float hi) {
    u64 r; asm("mov.b64 %0,{%1,%2};" : "=l"(r) : "f"(lo), "f"(hi)); return r;
}
__device__ __forceinline__ void unpack2(u64 v, float& lo, float& hi) {
    asm("mov.b64 {%0,%1},%2;" : "=f"(lo), "=f"(hi) : "l"(v));
}
__device__ __forceinline__ u64 fma2(u64 a, u64 b, u64 c) {
    u64 d; asm("fma.rn.f32x2 %0,%1,%2,%3;" : "=l"(d) : "l"(a), "l"(b), "l"(c)); return d;
}

// ---------------- scratch (device globals; no allocations) ----------------
__device__ float g_bufA[4u * 256u * 64u * 64u];     // 16.8 MB
__device__ float g_bufB[4u * 256u * 64u * 64u];     // 16.8 MB
__device__ float g_V[16u * 256u * 4096u];           // 67 MB (Winograd V)
__device__ float g_M[16u * 256u * 4096u];           // 67 MB (Winograd M)
__device__ float g_U[9u * 1024u * 1024u];           // 36 MB (all layers' U)
__device__ float2 g_bnpart[8192];                   // per-block BN partials
__device__ float g_warp[4 * 2 * 64 * 64];
__device__ float g_stats[1024];                     // [mean(C) | rstd(C)]

// U offsets per layer (floats)
#define UO1  0u
#define UO2  1327104u      // + 36*144*256
#define UO3  3686400u      // + 36*256*256
#define UO4  6045696u
#define UF1  8404992u
#define UF2  8552448u      // + 36*64*64
#define UF3  8699904u
#define UF4  8847360u

// ---------------------------------------------------------------------------
// Kernel 1: fused correlation + softmax + expected grid position
// ---------------------------------------------------------------------------
__global__ __launch_bounds__(128) void corr_kernel(
    const float* __restrict__ f0, const float* __restrict__ f1,
    float* __restrict__ warp)
{
    const int b  = blockIdx.x >> 7;
    const int p0 = (blockIdx.x & 127) * 32;

    __shared__ __align__(16) float f0_s[64][32];
    __shared__ __align__(16) float f1_sc[64 * 128];
    __shared__ float m_s[32], l_s[32], sx_s[32], sy_s[32];

    const int t    = threadIdx.x;
    const int tx   = t & 15;
    const int ty   = t >> 4;
    const int q    = t >> 2;
    const int quad = t & 3;

    for (int i = t; i < 64 * 32; i += 128) {
        int p = i & 31, c = i >> 5;
        f0_s[c][p] = f0[(b * 64 + c) * 4096 + p0 + p];
    }
    if (t < 32) { m_s[t] = -1e30f; l_s[t] = 0.f; sx_s[t] = 0.f; sy_s[t] = 0.f; }
    __syncthreads();

    for (int j0 = 0; j0 < 4096; j0 += 128) {
        for (int i = t; i < 64 * 128; i += 128) {
            int j = i & 127, c = i >> 7;
            f1_sc[c * 128 + j] = f1[(b * 64 + c) * 4096 + j0 + j];
        }
        __syncthreads();

        u64 acc2[4][4];
        #pragma unroll
        for (int i = 0; i < 4; i++)
            #pragma unroll
            for (int jp = 0; jp < 4; jp++) acc2[i][jp] = 0ull;

        #pragma unroll 16
        for (int c = 0; c < 64; c++) {
            float4 a0 = *(const float4*)&f0_s[c][ty * 4];
            u64 ap[4] = { pack2(a0.x, a0.x), pack2(a0.y, a0.y),
                          pack2(a0.z, a0.z), pack2(a0.w, a0.w) };
            const u64* bp = (const u64*)&f1_sc[c * 128 + tx * 8];
            u64 b0 = bp[0], b1 = bp[1], b2 = bp[2], b3 = bp[3];
            #pragma unroll
            for (int i = 0; i < 4; i++) {
                acc2[i][0] = fma2(ap[i], b0, acc2[i][0]);
                acc2[i][1] = fma2(ap[i], b1, acc2[i][1]);
                acc2[i][2] = fma2(ap[i], b2, acc2[i][2]);
                acc2[i][3] = fma2(ap[i], b3, acc2[i][3]);
            }
        }
        __syncthreads();

        #pragma unroll
        for (int i = 0; i < 4; i++)
            #pragma unroll
            for (int jp = 0; jp < 4; jp++) {
                float lo, hi; unpack2(acc2[i][jp], lo, hi);
                f1_sc[(ty * 4 + i) * 132 + tx * 8 + 2 * jp]     = lo * 0.125f;
                f1_sc[(ty * 4 + i) * 132 + tx * 8 + 2 * jp + 1] = hi * 0.125f;
            }
        __syncthreads();

        float m_old = m_s[q];
        float sc[32];
        float tm = -1e30f;
        #pragma unroll
        for (int i = 0; i < 32; i++) {
            sc[i] = f1_sc[q * 132 + quad + 4 * i];
            tm = fmaxf(tm, sc[i]);
        }
        tm = fmaxf(tm, __shfl_xor_sync(0xffffffffu, tm, 1));
        tm = fmaxf(tm, __shfl_xor_sync(0xffffffffu, tm, 2));
        float nm = fmaxf(m_old, tm);

        float le = 0.f, lx = 0.f, ly = 0.f;
        #pragma unroll
        for (int i = 0; i < 32; i++) {
            int j   = j0 + quad + 4 * i;
            float e = __expf(sc[i] - nm);
            float gx = (float)((j & 63) * 2 + 1) * (1.f / 64.f) - 1.f;
            float gy = (float)((j >> 6) * 2 + 1) * (1.f / 64.f) - 1.f;
            le += e;
            lx = fmaf(e, gx, lx);
            ly = fmaf(e, gy, ly);
        }
        le += __shfl_xor_sync(0xffffffffu, le, 1);
        le += __shfl_xor_sync(0xffffffffu, le, 2);
        lx += __shfl_xor_sync(0xffffffffu, lx, 1);
        lx += __shfl_xor_sync(0xffffffffu, lx, 2);
        ly += __shfl_xor_sync(0xffffffffu, ly, 1);
        ly += __shfl_xor_sync(0xffffffffu, ly, 2);

        if (quad == 0) {
            float s = __expf(m_old - nm);
            l_s[q]  = l_s[q]  * s + le;
            sx_s[q] = sx_s[q] * s + lx;
            sy_s[q] = sy_s[q] * s + ly;
            m_s[q]  = nm;
        }
        __syncthreads();
    }

    if (t < 32) {
        float inv = 1.f / l_s[t];
        warp[(b * 2 + 0) * 4096 + p0 + t] = sx_s[t] * inv;
        warp[(b * 2 + 1) * 4096 + p0 + t] = sy_s[t] * inv;
    }
}

// ===========================================================================
// Winograd F(4x4, 3x3)
// ===========================================================================

__device__ __forceinline__ void gmul(float a0, float a1, float a2, float o[6]) {
    o[0] = 0.25f * a0;
    o[1] = (-1.f / 6.f) * (a0 + a1 + a2);
    o[2] = (1.f / 6.f) * (-a0 + a1 - a2);
    o[3] = (1.f / 24.f) * a0 + (1.f / 12.f) * a1 + (1.f / 6.f) * a2;
    o[4] = (1.f / 24.f) * a0 - (1.f / 12.f) * a1 + (1.f / 6.f) * a2;
    o[5] = a2;
}

// --- one fused weight transform for ALL 8 layers ---------------------------
__global__ void wino_wtrans_all(
    const float* __restrict__ cw1, const float* __restrict__ cw2,
    const float* __restrict__ cw3, const float* __restrict__ cw4,
    const float* __restrict__ fw1, const float* __restrict__ fw2,
    const float* __restrict__ fw3, const float* __restrict__ fw4,
    float* __restrict__ U)
{
    int idx = blockIdx.x * blockDim.x + threadIdx.x;
    const float* w; int Cin, K, Co; unsigned base;
    if      (idx < 36864)  { w = cw1; Cin = 130; K = 144; Co = 256; base = UO1; }
    else if (idx < 102400) { w = cw2; Cin = 256; K = 256; Co = 256; base = UO2; idx -= 36864; }
    else if (idx < 167936) { w = cw3; Cin = 256; K = 256; Co = 256; base = UO3; idx -= 102400; }
    else if (idx < 233472) { w = cw4; Cin = 256; K = 256; Co = 256; base = UO4; idx -= 167936; }
    else if (idx < 237568) { w = fw1; Cin = 50;  K = 64;  Co = 64;  base = UF1; idx -= 233472; }
    else if (idx < 241664) { w = fw2; Cin = 64;  K = 64;  Co = 64;  base = UF2; idx -= 237568; }
    else if (idx < 245760) { w = fw3; Cin = 64;  K = 64;  Co = 64;  base = UF3; idx -= 241664; }
    else if (idx < 249856) { w = fw4; Cin = 64;  K = 64;  Co = 64;  base = UF4; idx -= 245760; }
    else return;

    int co = idx % Co;
    int ci = idx / Co;

    float g[3][3];
    #pragma unroll
    for (int i = 0; i < 3; i++)
        #pragma unroll
        for (int j = 0; j < 3; j++)
            g[i][j] = (ci < Cin) ? w[(co * Cin + ci) * 9 + i * 3 + j] : 0.f;

    float u[6][3];
    #pragma unroll
    for (int j = 0; j < 3; j++) {
        float col[6];
        gmul(g[0][j], g[1][j], g[2][j], col);
        #pragma unroll
        for (int i = 0; i < 6; i++) u[i][j] = col[i];
    }
    #pragma unroll
    for (int i = 0; i < 6; i++) {
        float row[6];
        gmul(u[i][0], u[i][1], u[i][2], row);
        #pragma unroll
        for (int j = 0; j < 6; j++)
            U[base + ((size_t)(i * 6 + j) * K + ci) * Co + co] = row[j];
    }
}

__device__ __forceinline__ void btmul(const float x[6], float y[6]) {
    y[0] =  4.f * x[0] - 5.f * x[2] + x[4];
    y[1] = -4.f * x[1] - 4.f * x[2] + x[3] + x[4];
    y[2] =  4.f * x[1] - 4.f * x[2] - x[3] + x[4];
    y[3] = -2.f * x[1] -       x[2] + 2.f * x[3] + x[4];
    y[4] =  2.f * x[1] -       x[2] - 2.f * x[3] + x[4];
    y[5] =  4.f * x[1] - 5.f * x[3] + x[5];
}

// --- input transform: V = B^T d B; BN fold computed inline from partials ---
// Grid is exactly K*T/256 blocks; T % 256 == 0 so each block touches ONE ci.
__global__ __launch_bounds__(256) void wino_intrans(
    const float* __restrict__ in, const float2* __restrict__ part,
    int nparts, float invN, float* __restrict__ V,
    int Cin, int K, int H, int W, int tilesW, int T)
{
    int idx = blockIdx.x * 256 + threadIdx.x;
    int n  = idx % T;
    int ci = idx / T;

    __shared__ float s_mu, s_rs;
    const bool hasBN = (part != nullptr);
    if (hasBN) {
        if (threadIdx.x == 0) {
            int c0 = (blockIdx.x * 256) / T;
            if (c0 < Cin) {
                float s = 0.f, sq = 0.f;
                for (int j = 0; j < nparts; j++) {
                    float2 v = part[c0 * nparts + j];
                    s += v.x; sq += v.y;
                }
                float m   = s * invN;
                float var = sq * invN - m * m;
                s_mu = m;
                s_rs = rsqrtf(var + 1e-5f);
            } else { s_mu = 0.f; s_rs = 1.f; }
        }
        __syncthreads();
    }

    int tilesH = H >> 2;
    int tpb = tilesW * tilesH;
    int b  = n / tpb;
    int r  = n - b * tpb;
    int th = r / tilesW;
    int tw = r - th * tilesW;

    float d[6][6];
    if (ci < Cin) {
        const float* ip = in + ((size_t)b * Cin + ci) * H * W;
        float mu = hasBN ? s_mu : 0.f;
        float rs = hasBN ? s_rs : 0.f;
        int h0 = th * 4 - 1, w0 = tw * 4 - 1;
        #pragma unroll
        for (int i = 0; i < 6; i++) {
            int h = h0 + i;
            #pragma unroll
            for (int j = 0; j < 6; j++) {
                int w = w0 + j;
                float v = 0.f;
                if ((unsigned)h < (unsigned)H && (unsigned)w < (unsigned)W) {
                    v = ip[h * W + w];
                    if (hasBN) v = fmaxf((v - mu) * rs, 0.f);
                }
                d[i][j] = v;
            }
        }
    } else {
        #pragma unroll
        for (int i = 0; i < 6; i++)
            #pragma unroll
            for (int j = 0; j < 6; j++) d[i][j] = 0.f;
    }

    float tt[6][6];
    #pragma unroll
    for (int j = 0; j < 6; j++) {
        float col[6] = { d[0][j], d[1][j], d[2][j], d[3][j], d[4][j], d[5][j] };
        float o[6];
        btmul(col, o);
        #pragma unroll
        for (int i = 0; i < 6; i++) tt[i][j] = o[i];
    }
    float* Vp = V + (size_t)ci * T + n;
    size_t ps = (size_t)K * T;
    #pragma unroll
    for (int i = 0; i < 6; i++) {
        float o[6];
        btmul(tt[i], o);
        #pragma unroll
        for (int j = 0; j < 6; j++)
            Vp[(size_t)(i * 6 + j) * ps] = o[j];
    }
}

// --- 36 batched GEMMs, 64co x 128n, 8x4/thread, FFMA2 (f32x2) inner loop ---
// Accumulators paired along co: acc2[cp][j] = (co=tc+2cp, co=tc+2cp+1) at n=tn+j.
// A pairs come free via LDS.64 of adjacent co; only B needs 4 dup-packs/k.
__global__ __launch_bounds__(256) void wino_gemm(
    const float* __restrict__ U, const float* __restrict__ V,
    float* __restrict__ M, int K, int Co, int T)
{
    const int xi = blockIdx.z;
    const int nb = blockIdx.x * 128;
    const int cb = blockIdx.y * 64;
    const float* Up = U + (size_t)xi * K * Co;
    const float* Vp = V + (size_t)xi * K * T;
    float*       Mp = M + (size_t)xi * Co * T;

    __shared__ __align__(16) float Us[2][16][64];
    __shared__ __align__(16) float Vs[2][16][128];

    const int t  = threadIdx.x;
    const int tn = (t & 31) * 4;
    const int tc = (t >> 5) * 8;

    const int ukk = (t * 4) >> 6, ucc = (t * 4) & 63;
    const int vkk = (t * 8) >> 7, vnn = (t * 8) & 127;

    u64 acc2[4][4];
    #pragma unroll
    for (int i = 0; i < 4; i++)
        #pragma unroll
        for (int j = 0; j < 4; j++) acc2[i][j] = 0ull;

    float4 ru, rv0, rv1;
    // prologue: chunk 0 -> buffer 0
    ru  = *(const float4*)&Up[(size_t)ukk * Co + cb + ucc];
    rv0 = *(const float4*)&Vp[(size_t)vkk * T + nb + vnn];
    rv1 = *(const float4*)&Vp[(size_t)vkk * T + nb + vnn + 4];
    *(float4*)&Us[0][ukk][ucc]     = ru;
    *(float4*)&Vs[0][vkk][vnn]     = rv0;
    *(float4*)&Vs[0][vkk][vnn + 4] = rv1;
    __syncthreads();

    const int nChunks = K >> 4;
    for (int c = 0; c < nChunks; c++) {
        const int cur = c & 1;
        if (c + 1 < nChunks) {
            int k0 = (c + 1) * 16;
            ru  = *(const float4*)&Up[(size_t)(k0 + ukk) * Co + cb + ucc];
            rv0 = *(const float4*)&Vp[(size_t)(k0 + vkk) * T + nb + vnn];
            rv1 = *(const float4*)&Vp[(size_t)(k0 + vkk) * T + nb + vnn + 4];
        }

        const float (*us)[64]  = Us[cur];
        const float (*vs)[128] = Vs[cur];
        #pragma unroll
        for (int k = 0; k < 16; k++) {
            const u64* ap = (const u64*)&us[k][tc];   // co pairs, aligned
            u64 a0 = ap[0], a1 = ap[1], a2 = ap[2], a3 = ap[3];
            float4 blf = *(const float4*)&vs[k][tn];
            u64 b0 = pack2(blf.x, blf.x);
            u64 b1 = pack2(blf.y, blf.y);
            u64 b2 = pack2(blf.z, blf.z);
            u64 b3 = pack2(blf.w, blf.w);
            acc2[0][0] = fma2(a0, b0, acc2[0][0]);
            acc2[0][1] = fma2(a0, b1, acc2[0][1]);
            acc2[0][2] = fma2(a0, b2, acc2[0][2]);
            acc2[0][3] = fma2(a0, b3, acc2[0][3]);
            acc2[1][0] = fma2(a1, b0, acc2[1][0]);
            acc2[1][1] = fma2(a1, b1, acc2[1][1]);
            acc2[1][2] = fma2(a1, b2, acc2[1][2]);
            acc2[1][3] = fma2(a1, b3, acc2[1][3]);
            acc2[2][0] = fma2(a2, b0, acc2[2][0]);
            acc2[2][1] = fma2(a2, b1, acc2[2][1]);
            acc2[2][2] = fma2(a2, b2, acc2[2][2]);
            acc2[2][3] = fma2(a2, b3, acc2[2][3]);
            acc2[3][0] = fma2(a3, b0, acc2[3][0]);
            acc2[3][1] = fma2(a3, b1, acc2[3][1]);
            acc2[3][2] = fma2(a3, b2, acc2[3][2]);
            acc2[3][3] = fma2(a3, b3, acc2[3][3]);
        }

        if (c + 1 < nChunks) {
            *(float4*)&Us[cur ^ 1][ukk][ucc]     = ru;
            *(float4*)&Vs[cur ^ 1][vkk][vnn]     = rv0;
            *(float4*)&Vs[cur ^ 1][vkk][vnn + 4] = rv1;
            __syncthreads();
        }
    }

    #pragma unroll
    for (int cp = 0; cp < 4; cp++) {
        float lo0, hi0, lo1, hi1, lo2, hi2, lo3, hi3;
        unpack2(acc2[cp][0], lo0, hi0);
        unpack2(acc2[cp][1], lo1, hi1);
        unpack2(acc2[cp][2], lo2, hi2);
        unpack2(acc2[cp][3], lo3, hi3);
        *(float4*)&Mp[(size_t)(cb + tc + 2 * cp)     * T + nb + tn] =
            make_float4(lo0, lo1, lo2, lo3);
        *(float4*)&Mp[(size_t)(cb + tc + 2 * cp + 1) * T + nb + tn] =
            make_float4(hi0, hi1, hi2, hi3);
    }
}

__device__ __forceinline__ void atmul(const float m[6], float y[4]) {
    y[0] = m[0] + m[1] + m[2] + m[3] + m[4];
    y[1] = m[1] - m[2] + 2.f * m[3] - 2.f * m[4];
    y[2] = m[1] + m[2] + 4.f * m[3] + 4.f * m[4];
    y[3] = m[1] - m[2] + 8.f * m[3] - 8.f * m[4] + m[5];
}

// --- output transform + block-reduced BN partial (1 per block) -------------
// Grid = Co*T/256; T % 256 == 0 so each block covers ONE co.
__global__ __launch_bounds__(256) void wino_outtrans(
    const float* __restrict__ M, float* __restrict__ out,
    float2* __restrict__ part, int Co, int H, int W, int tilesW, int T)
{
    int idx = blockIdx.x * 256 + threadIdx.x;
    int n  = idx % T;
    int co = idx / T;

    int tilesH = H >> 2;
    int tpb = tilesW * tilesH;
    int b  = n / tpb;
    int r  = n - b * tpb;
    int th = r / tilesW;
    int tw = r - th * tilesW;

    float m[6][6];
    const float* Mp = M + (size_t)co * T + n;
    size_t ps = (size_t)Co * T;
    #pragma unroll
    for (int i = 0; i < 6; i++)
        #pragma unroll
        for (int j = 0; j < 6; j++)
            m[i][j] = Mp[(size_t)(i * 6 + j) * ps];

    float s[4][6];
    #pragma unroll
    for (int j = 0; j < 6; j++) {
        float col[6] = { m[0][j], m[1][j], m[2][j], m[3][j], m[4][j], m[5][j] };
        float o[4];
        atmul(col, o);
        #pragma unroll
        for (int i = 0; i < 4; i++) s[i][j] = o[i];
    }

    float sum = 0.f, sq = 0.f;
    float* op = out + (((size_t)b * Co + co) * H + th * 4) * W + tw * 4;
    #pragma unroll
    for (int i = 0; i < 4; i++) {
        float o[4];
        atmul(s[i], o);
        op[i * W + 0] = o[0];
        op[i * W + 1] = o[1];
        op[i * W + 2] = o[2];
        op[i * W + 3] = o[3];
        #pragma unroll
        for (int j = 0; j < 4; j++) { sum += o[j]; sq = fmaf(o[j], o[j], sq); }
    }

    #pragma unroll
    for (int off = 16; off > 0; off >>= 1) {
        sum += __shfl_xor_sync(0xffffffffu, sum, off);
        sq  += __shfl_xor_sync(0xffffffffu, sq,  off);
    }
    __shared__ float2 red[8];
    if ((threadIdx.x & 31) == 0) red[threadIdx.x >> 5] = make_float2(sum, sq);
    __syncthreads();
    if (threadIdx.x == 0) {
        float ts = 0.f, tq = 0.f;
        #pragma unroll
        for (int i = 0; i < 8; i++) { ts += red[i].x; tq += red[i].y; }
        part[blockIdx.x] = make_float2(ts, tq);
    }
}

// --- finalize BN stats from partials (for the 1x1 heads) -------------------
__global__ void bn_finalize(const float2* __restrict__ part, float* __restrict__ stats,
                            int C, int nparts, float invN)
{
    int c = threadIdx.x;
    if (c >= C) return;
    float s = 0.f, sq = 0.f;
    for (int j = 0; j < nparts; j++) {
        float2 v = part[c * nparts + j];
        s += v.x; sq += v.y;
    }
    float m   = s * invN;
    float var = sq * invN - m * m;
    stats[c]     = m;
    stats[C + c] = rsqrtf(var + 1e-5f);
}

// ---------------------------------------------------------------------------
// fused concat assembly (copy + gridsample + coords)
// ---------------------------------------------------------------------------
__device__ __forceinline__ float gs_sample(const float* __restrict__ ip,
                                           float gx, float gy, int H, int W)
{
    float x = (gx + 1.f) * (W * 0.5f) - 0.5f;
    float y = (gy + 1.f) * (H * 0.5f) - 0.5f;
    float x0f = floorf(x), y0f = floorf(y);
    float wx = x - x0f, wy = y - y0f;
    int x0 = (int)x0f, y0 = (int)y0f;
    auto samp = [&](int yi, int xi) -> float {
        bool valid = (xi >= 0) && (xi < W) && (yi >= 0) && (yi < H);
        int yc = min(max(yi, 0), H - 1);
        int xc = min(max(xi, 0), W - 1);
        return valid ? ip[yc * W + xc] : 0.f;
    };
    return samp(y0,     x0    ) * (1.f - wx) * (1.f - wy)
         + samp(y0,     x0 + 1) * wx         * (1.f - wy)
         + samp(y0 + 1, x0    ) * (1.f - wx) * wy
         + samp(y0 + 1, x0 + 1) * wx         * wy;
}

__global__ void concat_coarse(const float* __restrict__ f0c, const float* __restrict__ f1c,
                              const float* __restrict__ warp, float* __restrict__ dst)
{
    const int HW = 4096;
    int idx = blockIdx.x * blockDim.x + threadIdx.x;
    if (idx >= 4 * 130 * HW) return;
    int p = idx % HW;
    int c = (idx / HW) % 130;
    int b = idx / (HW * 130);

    float v;
    if (c < 64) {
        v = f0c[((size_t)b * 64 + c) * HW + p];
    } else if (c < 128) {
        float gx = warp[(b * 2 + 0) * HW + p];
        float gy = warp[(b * 2 + 1) * HW + p];
        v = gs_sample(f1c + ((size_t)b * 64 + (c - 64)) * HW, gx, gy, 64, 64);
    } else {
        v = warp[(b * 2 + (c - 128)) * HW + p];
    }
    dst[((size_t)b * 130 + c) * HW + p] = v;
}

__global__ void concat_fine(const float* __restrict__ f0f, const float* __restrict__ f1f,
                            const float* __restrict__ up, float* __restrict__ dst)
{
    const int HW = 16384;
    int idx = blockIdx.x * blockDim.x + threadIdx.x;
    if (idx >= 4 * 50 * HW) return;
    int p = idx % HW;
    int c = (idx / HW) % 50;
    int b = idx / (HW * 50);

    float v;
    if (c < 24) {
        v = f0f[((size_t)b * 24 + c) * HW + p];
    } else if (c < 48) {
        float gx = up[((size_t)b * 3 + 0) * HW + p];
        float gy = up[((size_t)b * 3 + 1) * HW + p];
        v = gs_sample(f1f + ((size_t)b * 24 + (c - 24)) * HW, gx, gy, 128, 128);
    } else {
        v = up[((size_t)b * 3 + (c - 48)) * HW + p];
    }
    dst[((size_t)b * 50 + c) * HW + p] = v;
}

// ---------------------------------------------------------------------------
__global__ void upsample2x_kernel(const float* __restrict__ src, float* __restrict__ dst,
                                  int B_, int C, int Hi, int Wi)
{
    int Ho = Hi * 2, Wo = Wi * 2;
    int idx = blockIdx.x * blockDim.x + threadIdx.x;
    if (idx >= B_ * C * Ho * Wo) return;
    int wo = idx % Wo;
    int ho = (idx / Wo) % Ho;
    int bc = idx / (Wo * Ho);

    float sy = ho * 0.5f - 0.25f;
    float sx = wo * 0.5f - 0.25f;
    float fy = sy - floorf(sy);
    float fx = sx - floorf(sx);
    int y0 = (int)floorf(sy), x0 = (int)floorf(sx);
    int y0c = min(max(y0, 0), Hi - 1), y1c = min(max(y0 + 1, 0), Hi - 1);
    int x0c = min(max(x0, 0), Wi - 1), x1c = min(max(x0 + 1, 0), Wi - 1);

    const float* sp = src + bc * Hi * Wi;
    float v = sp[y0c * Wi + x0c] * (1.f - fy) * (1.f - fx)
            + sp[y0c * Wi + x1c] * (1.f - fy) * fx
            + sp[y1c * Wi + x0c] * fy * (1.f - fx)
            + sp[y1c * Wi + x1c] * fy * fx;
    dst[idx] = v;
}

// 1x1 conv to 3 ch + bias + base add, BN+ReLU fold, channel-split for ILP.
// Block: 32 pixels x 8 channel-groups (256 thr). Grid: B*HW/32.
__global__ __launch_bounds__(256) void conv1x1_3_kernel(
    const float* __restrict__ x, const float* __restrict__ stats,
    const float* __restrict__ w5, const float* __restrict__ b5,
    const float* __restrict__ base, int baseC, int baseStrideB,
    float* __restrict__ out, int Cin, int HW, int B_)
{
    const int lane = threadIdx.x & 31;
    const int g    = threadIdx.x >> 5;          // 0..7
    const int pix  = blockIdx.x * 32 + lane;
    const int b = pix / HW, p = pix - b * HW;
    const int cpg = Cin >> 3;
    const int c0  = g * cpg;

    float a0 = 0.f, a1 = 0.f, a2 = 0.f;
    const float* xp = x + ((size_t)b * Cin + c0) * HW + p;
    for (int i = 0; i < cpg; i++) {
        int ci = c0 + i;
        float v = xp[(size_t)i * HW];
        v = fmaxf((v - __ldg(&stats[ci])) * __ldg(&stats[Cin + ci]), 0.f);
        a0 = fmaf(v, __ldg(&w5[ci]),            a0);
        a1 = fmaf(v, __ldg(&w5[Cin + ci]),      a1);
        a2 = fmaf(v, __ldg(&w5[2 * Cin + ci]),  a2);
    }

    __shared__ float r[3][8][32];
    r[0][g][lane] = a0;
    r[1][g][lane] = a1;
    r[2][g][lane] = a2;
    __syncthreads();

    if (g == 0) {
        float s0 = 0.f, s1 = 0.f, s2 = 0.f;
        #pragma unroll
        for (int j = 0; j < 8; j++) {
            s0 += r[0][j][lane];
            s1 += r[1][j][lane];
            s2 += r[2][j][lane];
        }
        float b0v = base[b * baseStrideB + p];
        float b1v = base[b * baseStrideB + HW + p];
        float b2v = (baseC > 2) ? base[b * baseStrideB + 2 * HW + p] : 0.f;

        out[(size_t)b * 3 * HW + p]           = s0 + __ldg(&b5[0]) + b0v;
        out[(size_t)b * 3 * HW + HW + p]      = s1 + __ldg(&b5[1]) + b1v;
        out[(size_t)b * 3 * HW + 2 * HW + p]  = s2 + __ldg(&b5[2]) + b2v;
    }
}

// ---------------------------------------------------------------------------
// host-side helper: one Winograd F(4,3) conv layer (+ fused BN handling)
// ---------------------------------------------------------------------------
static void wino_layer(const float* x, const float* Ubase, const float2* partIn,
                       float* out, float* V, float* M, float2* partOut,
                       int Cin, int K, int Co, int H, int W)
{
    int tilesW = W >> 2, tilesH = H >> 2;
    int T = 4 * tilesW * tilesH;
    float invN = 1.f / (float)(T * 16);

    wino_intrans<<<K * T / 256, 256>>>(x, partIn, T / 256, invN, V,
                                       Cin, K, H, W, tilesW, T);
    dim3 gg(T / 128, Co / 64, 36);
    wino_gemm<<<gg, 256>>>(Ubase, V, M, K, Co, T);
    wino_outtrans<<<Co * T / 256, 256>>>(M, out, partOut, Co, H, W, tilesW, T);
}

// ---------------------------------------------------------------------------
extern "C" void kernel_launch(void* const* d_in, const int* in_sizes, int n_in,
                              void* d_out, int out_size)
{
    const float* f0c = (const float*)d_in[0];
    const float* f1c = (const float*)d_in[1];
    const float* f0f = (const float*)d_in[2];
    const float* f1f = (const float*)d_in[3];
    const float* cw1 = (const float*)d_in[4];
    const float* cw2 = (const float*)d_in[5];
    const float* cw3 = (const float*)d_in[6];
    const float* cw4 = (const float*)d_in[7];
    const float* cw5 = (const float*)d_in[8];
    const float* cb5 = (const float*)d_in[9];
    const float* fw1 = (const float*)d_in[10];
    const float* fw2 = (const float*)d_in[11];
    const float* fw3 = (const float*)d_in[12];
    const float* fw4 = (const float*)d_in[13];
    const float* fw5 = (const float*)d_in[14];
    const float* fb5 = (const float*)d_in[15];

    float *A, *Bb, *V, *M, *U, *warp, *stats;
    float2* part;
    cudaGetSymbolAddress((void**)&A,     g_bufA);
    cudaGetSymbolAddress((void**)&Bb,    g_bufB);
    cudaGetSymbolAddress((void**)&V,     g_V);
    cudaGetSymbolAddress((void**)&M,     g_M);
    cudaGetSymbolAddress((void**)&U,     g_U);
    cudaGetSymbolAddress((void**)&part,  g_bnpart);
    cudaGetSymbolAddress((void**)&warp,  g_warp);
    cudaGetSymbolAddress((void**)&stats, g_stats);

    float* outC = (float*)d_out;                 // (4,3,64,64)
    float* outF = outC + 4 * 3 * 64 * 64;        // (4,3,128,128)

    const int HWc = 64 * 64, HWf = 128 * 128;

    // ---- all weight transforms up front (one kernel) ----
    wino_wtrans_all<<<(249856 + 255) / 256, 256>>>(cw1, cw2, cw3, cw4,
                                                   fw1, fw2, fw3, fw4, U);

    // ---- coarse stage ----
    corr_kernel<<<512, 128>>>(f0c, f1c, warp);

    concat_coarse<<<(4 * 130 * HWc + 255) / 256, 256>>>(f0c, f1c, warp, A);

    wino_layer(A,  U + UO1, nullptr, Bb, V, M, part, 130, 144, 256, 64, 64);
    wino_layer(Bb, U + UO2, part,    A,  V, M, part, 256, 256, 256, 64, 64);
    wino_layer(A,  U + UO3, part,    Bb, V, M, part, 256, 256, 256, 64, 64);
    wino_layer(Bb, U + UO4, part,    A,  V, M, part, 256, 256, 256, 64, 64);

    bn_finalize<<<1, 256>>>(part, stats, 256, 4, 1.f / 16384.f);
    conv1x1_3_kernel<<<4 * HWc / 32, 256>>>(
        A, stats, cw5, cb5, warp, 2, 2 * HWc, outC, 256, HWc, 4);

    // ---- fine stage ----
    upsample2x_kernel<<<(4 * 3 * HWf + 255) / 256, 256>>>(outC, outF, 4, 3, 64, 64);

    concat_fine<<<(4 * 50 * HWf + 255) / 256, 256>>>(f0f, f1f, outF, Bb);

    wino_layer(Bb, U + UF1, nullptr, A,  V, M, part, 50, 64, 64, 128, 128);
    wino_layer(A,  U + UF2, part,    Bb, V, M, part, 64, 64, 64, 128, 128);
    wino_layer(Bb, U + UF3, part,    A,  V, M, part, 64, 64, 64, 128, 128);
    wino_layer(A,  U + UF4, part,    Bb, V, M, part, 64, 64, 64, 128, 128);

    bn_finalize<<<1, 256>>>(part, stats, 64, 16, 1.f / 65536.f);
    conv1x1_3_kernel<<<4 * HWf / 32, 256>>>(
        Bb, stats, fw5, fb5, outF, 3, 3 * HWf, outF, 64, HWf, 4);
}